// round 8
// baseline (speedup 1.0000x reference)
#include <cuda_runtime.h>
#include <cuda_fp16.h>
#include <math.h>
#include <stdint.h>

#define FDIM 512
#define DDIM 128
#define NMAX 50048
#define EPSF 1e-5f

// Scratch (allocation-free rule: device globals)
__device__ float g_x[(size_t)NMAX * DDIM];      // encoded node features

__device__ __forceinline__ void mma16h(float* c, unsigned a0, unsigned a1,
                                       unsigned a2, unsigned a3,
                                       unsigned b0, unsigned b1) {
    asm volatile(
        "mma.sync.aligned.m16n8k16.row.col.f32.f16.f16.f32 "
        "{%0,%1,%2,%3},{%4,%5,%6,%7},{%8,%9},{%0,%1,%2,%3};"
        : "+f"(c[0]), "+f"(c[1]), "+f"(c[2]), "+f"(c[3])
        : "r"(a0), "r"(a1), "r"(a2), "r"(a3), "r"(b0), "r"(b1));
}
__device__ __forceinline__ float clipf(float v) {
    return fminf(1.0f, fmaxf(-1.0f, v));
}
__device__ __forceinline__ unsigned pack2h(float lo, float hi) {
    __half2 h = __floats2half2_rn(lo, hi);
    return *(unsigned*)&h;
}

// ---------------------------------------------------------------------------
// Kernel 1: encoder  x = clip(pos @ W_enc + b, -1, 1) via FP16 mma m16n8k16.
// 512 threads, tile 128x128, BK=32 (16 packed k2-words), double buffered,
// 16 warps as 4x4 grid, warp tile 32x32 (acc 32 regs, no spills).
// As: [row][k2] stride 20 words; Bs: [k2][n] word-swizzle n^(8*(k2&3)).
// ---------------------------------------------------------------------------
__global__ __launch_bounds__(512, 1)
void encoder_h(const float* __restrict__ pos, const float* __restrict__ W,
               const float* __restrict__ bias, int N) {
    __shared__ unsigned As[2][128 * 20];
    __shared__ unsigned Bs[2][16 * 128];

    const int t = threadIdx.x, lane = t & 31, w = t >> 5;
    const int lm = lane >> 2, lk = lane & 3;
    const int m0 = (w >> 2) * 32, n0 = (w & 3) * 32;
    const int m0g = blockIdx.x * 128;

    // staging mapping
    const int arow = t >> 2, aq = t & 3;          // A: row, k-quad (8 floats)
    const int bk2 = t >> 5, bn4 = (t & 31) * 4;   // B: k2-row, 4-col group
    const bool aok = (m0g + arow) < N;
    const float* ap = pos + (size_t)(m0g + arow) * FDIM + aq * 8;
    const float* bp = W + (size_t)(2 * bk2) * 128 + bn4;
    const int asoff = arow * 20 + aq * 4;
    const int bsoff = bk2 * 128 + (bn4 ^ (8 * (bk2 & 3)));

    float acc[2][4][4];
#pragma unroll
    for (int mf = 0; mf < 2; mf++)
#pragma unroll
        for (int nf = 0; nf < 4; nf++)
#pragma unroll
            for (int r = 0; r < 4; r++) acc[mf][nf][r] = 0.0f;

    unsigned ua[4], ub[4];
    // load + pack k-tile kt into registers
    auto loadp = [&](int kt) {
        if (aok) {
            float4 p0 = *(const float4*)(ap + kt * 32);
            float4 p1 = *(const float4*)(ap + kt * 32 + 4);
            ua[0] = pack2h(p0.x, p0.y); ua[1] = pack2h(p0.z, p0.w);
            ua[2] = pack2h(p1.x, p1.y); ua[3] = pack2h(p1.z, p1.w);
        } else {
            ua[0] = ua[1] = ua[2] = ua[3] = 0u;
        }
        const float* b0p = bp + (size_t)kt * 32 * 128;
        float4 q0 = *(const float4*)(b0p);
        float4 q1 = *(const float4*)(b0p + 128);
        ub[0] = pack2h(q0.x, q1.x); ub[1] = pack2h(q0.y, q1.y);
        ub[2] = pack2h(q0.z, q1.z); ub[3] = pack2h(q0.w, q1.w);
    };
    auto store_st = [&](int s) {
        *(uint4*)&As[s][asoff] = make_uint4(ua[0], ua[1], ua[2], ua[3]);
        *(uint4*)&Bs[s][bsoff] = make_uint4(ub[0], ub[1], ub[2], ub[3]);
    };

    loadp(0);
    store_st(0);
    __syncthreads();

    for (int kt = 0; kt < 16; kt++) {
        const int s = kt & 1;
        if (kt < 15) loadp(kt + 1);
#pragma unroll
        for (int ks = 0; ks < 2; ks++) {
            const int k20 = ks * 8;
            const int sw = 8 * lk;
            unsigned a[2][4];
#pragma unroll
            for (int mf = 0; mf < 2; mf++) {
                int rb = m0 + mf * 16;
                a[mf][0] = As[s][(rb + lm) * 20 + k20 + lk];
                a[mf][1] = As[s][(rb + lm + 8) * 20 + k20 + lk];
                a[mf][2] = As[s][(rb + lm) * 20 + k20 + lk + 4];
                a[mf][3] = As[s][(rb + lm + 8) * 20 + k20 + lk + 4];
            }
            unsigned b[4][2];
#pragma unroll
            for (int nf = 0; nf < 4; nf++) {
                int cb = n0 + nf * 8;
                b[nf][0] = Bs[s][(k20 + lk) * 128 + ((cb + lm) ^ sw)];
                b[nf][1] = Bs[s][(k20 + lk + 4) * 128 + ((cb + lm) ^ sw)];
            }
#pragma unroll
            for (int mf = 0; mf < 2; mf++)
#pragma unroll
                for (int nf = 0; nf < 4; nf++)
                    mma16h(acc[mf][nf], a[mf][0], a[mf][1], a[mf][2], a[mf][3],
                           b[nf][0], b[nf][1]);
        }
        if (kt < 15) {
            store_st(s ^ 1);
            __syncthreads();
        }
    }

    // epilogue: bias + hardtanh; g_x rows padded to NMAX so no store guard
#pragma unroll
    for (int mf = 0; mf < 2; mf++) {
        int r0 = m0g + m0 + mf * 16 + lm;
#pragma unroll
        for (int nf = 0; nf < 4; nf++) {
            int c = n0 + nf * 8 + 2 * lk;
            float b0 = __ldg(bias + c), b1 = __ldg(bias + c + 1);
            float2 v0, v1;
            v0.x = clipf(acc[mf][nf][0] + b0);
            v0.y = clipf(acc[mf][nf][1] + b1);
            v1.x = clipf(acc[mf][nf][2] + b0);
            v1.y = clipf(acc[mf][nf][3] + b1);
            *(float2*)&g_x[(size_t)r0 * 128 + c]       = v0;
            *(float2*)&g_x[(size_t)(r0 + 8) * 128 + c] = v1;
        }
    }
}

// ---------------------------------------------------------------------------
// Kernel 2: fused per-hyperedge pipeline, 16 edges/iter, FP16 mma m16n8k16.
// (UNCHANGED from R7 — controlled experiment: only encoder changes)
// ---------------------------------------------------------------------------
#define ESMEM 148480

__global__ __launch_bounds__(512, 1)
void edge_mma(const int* __restrict__ members, const float* __restrict__ chebW,
              const float* __restrict__ gamma_, const float* __restrict__ beta_,
              const float* __restrict__ alpha_, const float* __restrict__ chebb,
              const float* __restrict__ linW, const float* __restrict__ linb,
              float* __restrict__ out, int E) {
    extern __shared__ unsigned char esm[];
    unsigned* Acs = (unsigned*)esm;
    unsigned* Bcs = (unsigned*)(esm + 32768);
    unsigned* Gw  = (unsigned*)(esm + 65536);
    float*    Hs  = (float*)(esm + 65536);
    unsigned* Sw  = (unsigned*)(esm + 135168);
    float*    Qsm = (float*)(esm + 139520);
    float*    red = (float*)(esm + 148224);

    const int t = threadIdx.x;
    const int lane = t & 31, w = t >> 5;
    const int lm = lane >> 2, lk = lane & 3;

    // ---- fold of prep: A = W0 + W1/7 - 47/49 W2 ; B = -W1/7 + 12/49 W2 ----
    for (int i = t; i < 2048; i += 512) {
        int k2 = i >> 5;
        int cg = (i & 31) * 4;
        const float* p0 = chebW + (2 * k2) * 128 + cg;
        const float* p1 = p0 + 128;
        float4 w00 = __ldg((const float4*)(p0));
        float4 w01 = __ldg((const float4*)(p0 + 16384));
        float4 w02 = __ldg((const float4*)(p0 + 32768));
        float4 w10 = __ldg((const float4*)(p1));
        float4 w11 = __ldg((const float4*)(p1 + 16384));
        float4 w12 = __ldg((const float4*)(p1 + 32768));
        float a0[4] = {w00.x + w01.x*(1.0f/7.0f) - w02.x*(47.0f/49.0f),
                       w00.y + w01.y*(1.0f/7.0f) - w02.y*(47.0f/49.0f),
                       w00.z + w01.z*(1.0f/7.0f) - w02.z*(47.0f/49.0f),
                       w00.w + w01.w*(1.0f/7.0f) - w02.w*(47.0f/49.0f)};
        float a1[4] = {w10.x + w11.x*(1.0f/7.0f) - w12.x*(47.0f/49.0f),
                       w10.y + w11.y*(1.0f/7.0f) - w12.y*(47.0f/49.0f),
                       w10.z + w11.z*(1.0f/7.0f) - w12.z*(47.0f/49.0f),
                       w10.w + w11.w*(1.0f/7.0f) - w12.w*(47.0f/49.0f)};
        float b0[4] = {-w01.x*(1.0f/7.0f) + w02.x*(12.0f/49.0f),
                       -w01.y*(1.0f/7.0f) + w02.y*(12.0f/49.0f),
                       -w01.z*(1.0f/7.0f) + w02.z*(12.0f/49.0f),
                       -w01.w*(1.0f/7.0f) + w02.w*(12.0f/49.0f)};
        float b1[4] = {-w11.x*(1.0f/7.0f) + w12.x*(12.0f/49.0f),
                       -w11.y*(1.0f/7.0f) + w12.y*(12.0f/49.0f),
                       -w11.z*(1.0f/7.0f) + w12.z*(12.0f/49.0f),
                       -w11.w*(1.0f/7.0f) + w12.w*(12.0f/49.0f)};
        int dst = k2 * 128 + (cg ^ (8 * (k2 & 3)));
        uint4 ua = make_uint4(pack2h(a0[0], a1[0]), pack2h(a0[1], a1[1]),
                              pack2h(a0[2], a1[2]), pack2h(a0[3], a1[3]));
        uint4 ub = make_uint4(pack2h(b0[0], b1[0]), pack2h(b0[1], b1[1]),
                              pack2h(b0[2], b1[2]), pack2h(b0[3], b1[3]));
        *(uint4*)&Acs[dst] = ua;
        *(uint4*)&Bcs[dst] = ub;
    }

    const int c4 = t & 31;
    const float4 ga4 = *(const float4*)(gamma_ + 4 * c4);
    const float4 be4 = *(const float4*)(beta_  + 4 * c4);
    const float4 al4 = *(const float4*)(alpha_ + 4 * c4);

    const int d = t & 127, quarter = t >> 7;
    const float lw0 = linW[d], lw1 = linW[128 + d];
    const float lb = __ldg(linb);

    const int m0 = (w >> 2) * 32, n0 = (w & 3) * 32, nq0 = w * 8;
    const int nIter = (E + 15) >> 4;

    __syncthreads();   // Acs/Bcs ready

    for (int it = blockIdx.x; it < nIter; it += gridDim.x) {
        const int ebase = it * 16;

        const int el = w;
        const int e = ebase + el;
        int mreg = 0;
        if (lane < 8 && e < E) mreg = __ldg(&members[e * 8 + lane]);

        // ---- stage A: gather + GraphNorm -> fp16 Gw / Sw ----
        {
            unsigned* grow = Gw + el * 8 * 68 + 2 * c4;
            unsigned* srow = Sw + el * 68 + 2 * c4;
            if (e < E) {
                float4 xv[8];
#pragma unroll
                for (int i = 0; i < 8; i++) {
                    int node = __shfl_sync(0xffffffffu, mreg, i);
                    xv[i] = *(const float4*)(g_x + (size_t)node * 128 + 4 * c4);
                }
                float4 mean = make_float4(0, 0, 0, 0);
#pragma unroll
                for (int i = 0; i < 8; i++) {
                    mean.x += xv[i].x; mean.y += xv[i].y;
                    mean.z += xv[i].z; mean.w += xv[i].w;
                }
                mean.x *= 0.125f; mean.y *= 0.125f;
                mean.z *= 0.125f; mean.w *= 0.125f;
                float4 am = make_float4(al4.x * mean.x, al4.y * mean.y,
                                        al4.z * mean.z, al4.w * mean.w);
                float4 var = make_float4(0, 0, 0, 0);
#pragma unroll
                for (int i = 0; i < 8; i++) {
                    xv[i].x -= am.x; xv[i].y -= am.y;
                    xv[i].z -= am.z; xv[i].w -= am.w;
                    var.x += xv[i].x * xv[i].x; var.y += xv[i].y * xv[i].y;
                    var.z += xv[i].z * xv[i].z; var.w += xv[i].w * xv[i].w;
                }
                float4 inv;
                inv.x = ga4.x * rsqrtf(var.x * 0.125f + EPSF);
                inv.y = ga4.y * rsqrtf(var.y * 0.125f + EPSF);
                inv.z = ga4.z * rsqrtf(var.z * 0.125f + EPSF);
                inv.w = ga4.w * rsqrtf(var.w * 0.125f + EPSF);
#pragma unroll
                for (int i = 0; i < 8; i++) {
                    uint2 u;
                    u.x = pack2h(xv[i].x * inv.x + be4.x, xv[i].y * inv.y + be4.y);
                    u.y = pack2h(xv[i].z * inv.z + be4.z, xv[i].w * inv.w + be4.w);
                    *(uint2*)(grow + i * 68) = u;
                }
                uint2 su;
                su.x = pack2h(inv.x * 8.0f * mean.x * (1.0f - al4.x) + 8.0f * be4.x,
                              inv.y * 8.0f * mean.y * (1.0f - al4.y) + 8.0f * be4.y);
                su.y = pack2h(inv.z * 8.0f * mean.z * (1.0f - al4.z) + 8.0f * be4.z,
                              inv.w * 8.0f * mean.w * (1.0f - al4.w) + 8.0f * be4.w);
                *(uint2*)srow = su;
            } else {
                uint2 z = make_uint2(0, 0);
#pragma unroll
                for (int i = 0; i < 8; i++) *(uint2*)(grow + i * 68) = z;
                *(uint2*)srow = z;
            }
        }
        __syncthreads();

        // ---- stage B: fp16 MMAs. main: g[128,128]@A ; q: S[16,128]@B ----
        float acc[2][4][4];
        float qac[4];
#pragma unroll
        for (int mf = 0; mf < 2; mf++)
#pragma unroll
            for (int nf = 0; nf < 4; nf++)
#pragma unroll
                for (int r = 0; r < 4; r++) acc[mf][nf][r] = 0.0f;
#pragma unroll
        for (int r = 0; r < 4; r++) qac[r] = 0.0f;

#pragma unroll
        for (int ks = 0; ks < 8; ks++) {
            const int k20 = ks * 8;
            const int sw = 8 * lk;
            unsigned a[2][4];
#pragma unroll
            for (int mf = 0; mf < 2; mf++) {
                int rb = m0 + mf * 16;
                a[mf][0] = Gw[(rb + lm) * 68 + k20 + lk];
                a[mf][1] = Gw[(rb + lm + 8) * 68 + k20 + lk];
                a[mf][2] = Gw[(rb + lm) * 68 + k20 + lk + 4];
                a[mf][3] = Gw[(rb + lm + 8) * 68 + k20 + lk + 4];
            }
            unsigned b[4][2];
#pragma unroll
            for (int nf = 0; nf < 4; nf++) {
                int cb = n0 + nf * 8;
                b[nf][0] = Acs[(k20 + lk) * 128 + ((cb + lm) ^ sw)];
                b[nf][1] = Acs[(k20 + lk + 4) * 128 + ((cb + lm) ^ sw)];
            }
#pragma unroll
            for (int mf = 0; mf < 2; mf++)
#pragma unroll
                for (int nf = 0; nf < 4; nf++)
                    mma16h(acc[mf][nf], a[mf][0], a[mf][1], a[mf][2], a[mf][3],
                           b[nf][0], b[nf][1]);
            unsigned sa0 = Sw[lm * 68 + k20 + lk];
            unsigned sa1 = Sw[(lm + 8) * 68 + k20 + lk];
            unsigned sa2 = Sw[lm * 68 + k20 + lk + 4];
            unsigned sa3 = Sw[(lm + 8) * 68 + k20 + lk + 4];
            unsigned qb0 = Bcs[(k20 + lk) * 128 + ((nq0 + lm) ^ sw)];
            unsigned qb1 = Bcs[(k20 + lk + 4) * 128 + ((nq0 + lm) ^ sw)];
            mma16h(qac, sa0, sa1, sa2, sa3, qb0, qb1);
        }
        {
            int c = nq0 + 2 * lk;
            float cb0 = __ldg(chebb + c), cb1 = __ldg(chebb + c + 1);
            Qsm[lm * 136 + c]           = qac[0] + cb0;
            Qsm[lm * 136 + c + 1]       = qac[1] + cb1;
            Qsm[(lm + 8) * 136 + c]     = qac[2] + cb0;
            Qsm[(lm + 8) * 136 + c + 1] = qac[3] + cb1;
        }
        __syncthreads();

        // ---- stage C: h = clip(acc + Q[e][c]) -> Hs (reuses Gw space) ----
#pragma unroll
        for (int mf = 0; mf < 2; mf++) {
            int rb = m0 + mf * 16 + lm;
            int e0 = rb >> 3;
            int e1 = (rb + 8) >> 3;
#pragma unroll
            for (int nf = 0; nf < 4; nf++) {
                int c = n0 + nf * 8 + 2 * lk;
                float2 q0 = *(const float2*)&Qsm[e0 * 136 + c];
                float2 q1 = *(const float2*)&Qsm[e1 * 136 + c];
                float2 v0, v1;
                v0.x = clipf(acc[mf][nf][0] + q0.x);
                v0.y = clipf(acc[mf][nf][1] + q0.y);
                v1.x = clipf(acc[mf][nf][2] + q1.x);
                v1.y = clipf(acc[mf][nf][3] + q1.y);
                *(float2*)&Hs[rb * 136 + c]       = v0;
                *(float2*)&Hs[(rb + 8) * 136 + c] = v1;
            }
        }
        __syncthreads();

        // ---- stage D: pooling + linear head + sigmoid (4 edges / thread) ----
        float contrib[4];
#pragma unroll
        for (int j = 0; j < 4; j++) {
            int elj = quarter * 4 + j;
            float mx = -2.0f, mn = 2.0f, ss = 0.0f;
#pragma unroll
            for (int i = 0; i < 8; i++) {
                float h = Hs[(elj * 8 + i) * 136 + d];
                mx = fmaxf(mx, h);
                mn = fminf(mn, h);
                ss += h * h;
            }
            contrib[j] = (mx - mn) * lw0 + sqrtf(ss * 0.125f) * lw1;
        }
#pragma unroll
        for (int j = 0; j < 4; j++) {
            float v = contrib[j];
            v += __shfl_xor_sync(0xffffffffu, v, 16);
            v += __shfl_xor_sync(0xffffffffu, v, 8);
            v += __shfl_xor_sync(0xffffffffu, v, 4);
            v += __shfl_xor_sync(0xffffffffu, v, 2);
            v += __shfl_xor_sync(0xffffffffu, v, 1);
            if (lane == 0) red[(quarter * 4 + j) * 4 + (w & 3)] = v;
        }
        __syncthreads();
        if (t < 16) {
            int eo = ebase + t;
            if (eo < E) {
                float* r = red + t * 4;
                float logit = r[0] + r[1] + r[2] + r[3] + lb;
                out[eo] = 1.0f / (1.0f + expf(-logit));
            }
        }
        __syncthreads();   // protect smem before next iteration
    }
}

// ---------------------------------------------------------------------------
extern "C" void kernel_launch(void* const* d_in, const int* in_sizes, int n_in,
                              void* d_out, int out_size) {
    const float* pos   = (const float*)d_in[0];
    const float* Wenc  = (const float*)d_in[1];
    const float* benc  = (const float*)d_in[2];
    const float* gam   = (const float*)d_in[3];
    const float* bet   = (const float*)d_in[4];
    const float* alp   = (const float*)d_in[5];
    const float* chebW = (const float*)d_in[6];
    const float* chebb = (const float*)d_in[7];
    const float* linW  = (const float*)d_in[8];
    const float* linb  = (const float*)d_in[9];
    const int*   membs = (const int*)d_in[10];

    int N = in_sizes[0] / FDIM;   // 50000
    int E = in_sizes[10] / 8;     // 20000

    encoder_h<<<(N + 127) / 128, 512>>>(pos, Wenc, benc, N);

    cudaFuncSetAttribute(edge_mma, cudaFuncAttributeMaxDynamicSharedMemorySize,
                         ESMEM);
    int nIter = (E + 15) / 16;
    int grid = nIter < 148 ? nIter : 148;
    edge_mma<<<grid, 512, ESMEM>>>(membs, chebW, gam, bet, alp, chebb, linW,
                                   linb, (float*)d_out, E);
}

// round 9
// speedup vs baseline: 1.1111x; 1.1111x over previous
#include <cuda_runtime.h>
#include <cuda_fp16.h>
#include <math.h>
#include <stdint.h>

#define FDIM 512
#define DDIM 128
#define NMAX 50048
#define EPSF 1e-5f

// Scratch (allocation-free rule: device globals)
__device__ float g_x[(size_t)NMAX * DDIM];      // encoded node features

__device__ __forceinline__ unsigned f2tf(float x) {
    unsigned r; asm("cvt.rna.tf32.f32 %0, %1;" : "=r"(r) : "f"(x)); return r;
}
__device__ __forceinline__ void mma8(float* c, unsigned a0, unsigned a1,
                                     unsigned a2, unsigned a3,
                                     unsigned b0, unsigned b1) {
    asm volatile(
        "mma.sync.aligned.m16n8k8.row.col.f32.tf32.tf32.f32 "
        "{%0,%1,%2,%3},{%4,%5,%6,%7},{%8,%9},{%0,%1,%2,%3};"
        : "+f"(c[0]), "+f"(c[1]), "+f"(c[2]), "+f"(c[3])
        : "r"(a0), "r"(a1), "r"(a2), "r"(a3), "r"(b0), "r"(b1));
}
__device__ __forceinline__ void mma16h(float* c, unsigned a0, unsigned a1,
                                       unsigned a2, unsigned a3,
                                       unsigned b0, unsigned b1) {
    asm volatile(
        "mma.sync.aligned.m16n8k16.row.col.f32.f16.f16.f32 "
        "{%0,%1,%2,%3},{%4,%5,%6,%7},{%8,%9},{%0,%1,%2,%3};"
        : "+f"(c[0]), "+f"(c[1]), "+f"(c[2]), "+f"(c[3])
        : "r"(a0), "r"(a1), "r"(a2), "r"(a3), "r"(b0), "r"(b1));
}
__device__ __forceinline__ float clipf(float v) {
    return fminf(1.0f, fmaxf(-1.0f, v));
}
__device__ __forceinline__ unsigned pack2h(float lo, float hi) {
    __half2 h = __floats2half2_rn(lo, hi);
    return *(unsigned*)&h;
}
__device__ __forceinline__ uint32_t smem_u32(const void* p) {
    uint32_t a;
    asm("{ .reg .u64 t; cvta.to.shared.u64 t, %1; cvt.u32.u64 %0, t; }"
        : "=r"(a) : "l"(p));
    return a;
}
__device__ __forceinline__ void cpasync16(uint32_t dst, const void* src, int szr) {
    asm volatile("cp.async.ca.shared.global [%0], [%1], 16, %2;"
                 :: "r"(dst), "l"(src), "r"(szr) : "memory");
}
#define CP_COMMIT() asm volatile("cp.async.commit_group;" ::: "memory")
#define CP_WAIT1()  asm volatile("cp.async.wait_group 1;" ::: "memory")

// ---------------------------------------------------------------------------
// Kernel 1: encoder  x = clip(pos @ W_enc + b, -1, 1) via tf32 mma.sync.
// (REVERTED to R7 cp.async 3-stage pipeline — known good, ~52us)
// ---------------------------------------------------------------------------
#define ENC_A_BYTES (128 * 20 * 4)                    // 10240
#define ENC_B_BYTES (16 * 128 * 4)                    // 8192
#define ENC_SMEM    (3 * (ENC_A_BYTES + ENC_B_BYTES)) // 55296

__global__ __launch_bounds__(256, 2)
void encoder_cp(const float* __restrict__ pos, const float* __restrict__ W,
                const float* __restrict__ bias, int N) {
    extern __shared__ unsigned char sm[];
    const uint32_t smb = smem_u32(sm);

    const int t = threadIdx.x, lane = t & 31, w = t >> 5;
    const int wy = w >> 1, wx = w & 1;
    const int lm = lane >> 2, lk = lane & 3;
    const int m0 = blockIdx.x * 128;

    const int ar0 = t >> 2, akq = t & 3;
    const int bk0 = t >> 5, bnq = t & 31;

    float acc[2][8][4];
#pragma unroll
    for (int mf = 0; mf < 2; mf++)
#pragma unroll
        for (int nf = 0; nf < 8; nf++)
#pragma unroll
            for (int r = 0; r < 4; r++) acc[mf][nf][r] = 0.0f;

    auto issue = [&](int s, int kt) {
        const uint32_t abase = smb + s * ENC_A_BYTES;
        const uint32_t bbase = smb + 3 * ENC_A_BYTES + s * ENC_B_BYTES;
#pragma unroll
        for (int h = 0; h < 2; h++) {
            int r = ar0 + h * 64;
            const float* src = pos + (size_t)(m0 + r) * FDIM + kt * 16 + akq * 4;
            uint32_t dst = abase + (r * 20 + akq * 4) * 4;
            cpasync16(dst, src, (m0 + r) < N ? 16 : 0);
        }
#pragma unroll
        for (int h = 0; h < 2; h++) {
            int k = bk0 + h * 8;
            const float* src = W + (size_t)(kt * 16 + k) * 128 + bnq * 4;
            uint32_t dst = bbase + (k * 128 + ((bnq * 4) ^ (8 * (k & 3)))) * 4;
            cpasync16(dst, src, 16);
        }
    };

    issue(0, 0); CP_COMMIT();
    issue(1, 1); CP_COMMIT();

    for (int kt = 0; kt < 32; kt++) {
        const int s = kt % 3;
        CP_WAIT1();
        __syncthreads();
        if (kt + 2 < 32) issue((kt + 2) % 3, kt + 2);
        CP_COMMIT();

        const unsigned* As = (const unsigned*)(sm + s * ENC_A_BYTES);
        const unsigned* Bs = (const unsigned*)(sm + 3 * ENC_A_BYTES + s * ENC_B_BYTES);
#pragma unroll
        for (int kh = 0; kh < 2; kh++) {
            const int k0 = kh * 8;
            unsigned a[2][4], b[8][2];
#pragma unroll
            for (int mf = 0; mf < 2; mf++) {
                int rb = wy * 32 + mf * 16;
                a[mf][0] = As[(rb + lm) * 20 + k0 + lk];
                a[mf][1] = As[(rb + lm + 8) * 20 + k0 + lk];
                a[mf][2] = As[(rb + lm) * 20 + k0 + lk + 4];
                a[mf][3] = As[(rb + lm + 8) * 20 + k0 + lk + 4];
            }
#pragma unroll
            for (int nf = 0; nf < 8; nf++) {
                int cb = wx * 64 + nf * 8;
                b[nf][0] = Bs[(k0 + lk) * 128 + ((cb + lm) ^ (8 * lk))];
                b[nf][1] = Bs[(k0 + lk + 4) * 128 + ((cb + lm) ^ (8 * lk))];
            }
#pragma unroll
            for (int mf = 0; mf < 2; mf++)
#pragma unroll
                for (int nf = 0; nf < 8; nf++)
                    mma8(acc[mf][nf], a[mf][0], a[mf][1], a[mf][2], a[mf][3],
                         b[nf][0], b[nf][1]);
        }
    }

#pragma unroll
    for (int mf = 0; mf < 2; mf++) {
        int r0 = m0 + wy * 32 + mf * 16 + lm;
#pragma unroll
        for (int nf = 0; nf < 8; nf++) {
            int c = wx * 64 + nf * 8 + 2 * lk;
            float b0 = __ldg(bias + c), b1 = __ldg(bias + c + 1);
            if (r0 < N) {
                float2 v;
                v.x = clipf(acc[mf][nf][0] + b0);
                v.y = clipf(acc[mf][nf][1] + b1);
                *(float2*)&g_x[(size_t)r0 * 128 + c] = v;
            }
            if (r0 + 8 < N) {
                float2 v;
                v.x = clipf(acc[mf][nf][2] + b0);
                v.y = clipf(acc[mf][nf][3] + b1);
                *(float2*)&g_x[(size_t)(r0 + 8) * 128 + c] = v;
            }
        }
    }
}

// ---------------------------------------------------------------------------
// Kernel 2: fused per-hyperedge pipeline, 32 edges/iter, FP16 mma m16n8k16.
// R9: double the edge tile (halves per-edge sync/fixed costs).
// 512 threads, 16 warps, main MMA warp tile 64x32 (grid 4x4).
// smem layout (dynamic, 222720 B):
//   Acs  word[64*128]  @0       : Cheb A fp16, [k2][n] XOR-8(k2&3) swizzle
//   Bcs  word[64*128]  @32768   : Cheb B fp16
//   Gw   word[256*68]  @65536   : g fp16, [row][k2], stride 68 words
//   Hs   float[256*136]@65536   : (union w/ Gw) h fp32, stride 136
//   Sw   word[32*68]   @204800  : S fp16  (union with Qsm, disjoint lifetime)
//   Qsm  float[32*136] @204800  : q = S@B + chebb
//   red  float[32*4]   @222208
// ---------------------------------------------------------------------------
#define ESMEM 222720

__global__ __launch_bounds__(512, 1)
void edge_mma(const int* __restrict__ members, const float* __restrict__ chebW,
              const float* __restrict__ gamma_, const float* __restrict__ beta_,
              const float* __restrict__ alpha_, const float* __restrict__ chebb,
              const float* __restrict__ linW, const float* __restrict__ linb,
              float* __restrict__ out, int E) {
    extern __shared__ unsigned char esm[];
    unsigned* Acs = (unsigned*)esm;
    unsigned* Bcs = (unsigned*)(esm + 32768);
    unsigned* Gw  = (unsigned*)(esm + 65536);
    float*    Hs  = (float*)(esm + 65536);
    unsigned* Sw  = (unsigned*)(esm + 204800);
    float*    Qsm = (float*)(esm + 204800);
    float*    red = (float*)(esm + 222208);

    const int t = threadIdx.x;
    const int lane = t & 31, w = t >> 5;
    const int lm = lane >> 2, lk = lane & 3;

    // ---- fold of prep: A = W0 + W1/7 - 47/49 W2 ; B = -W1/7 + 12/49 W2 ----
    for (int i = t; i < 2048; i += 512) {
        int k2 = i >> 5;
        int cg = (i & 31) * 4;
        const float* p0 = chebW + (2 * k2) * 128 + cg;
        const float* p1 = p0 + 128;
        float4 w00 = __ldg((const float4*)(p0));
        float4 w01 = __ldg((const float4*)(p0 + 16384));
        float4 w02 = __ldg((const float4*)(p0 + 32768));
        float4 w10 = __ldg((const float4*)(p1));
        float4 w11 = __ldg((const float4*)(p1 + 16384));
        float4 w12 = __ldg((const float4*)(p1 + 32768));
        float a0[4] = {w00.x + w01.x*(1.0f/7.0f) - w02.x*(47.0f/49.0f),
                       w00.y + w01.y*(1.0f/7.0f) - w02.y*(47.0f/49.0f),
                       w00.z + w01.z*(1.0f/7.0f) - w02.z*(47.0f/49.0f),
                       w00.w + w01.w*(1.0f/7.0f) - w02.w*(47.0f/49.0f)};
        float a1[4] = {w10.x + w11.x*(1.0f/7.0f) - w12.x*(47.0f/49.0f),
                       w10.y + w11.y*(1.0f/7.0f) - w12.y*(47.0f/49.0f),
                       w10.z + w11.z*(1.0f/7.0f) - w12.z*(47.0f/49.0f),
                       w10.w + w11.w*(1.0f/7.0f) - w12.w*(47.0f/49.0f)};
        float b0[4] = {-w01.x*(1.0f/7.0f) + w02.x*(12.0f/49.0f),
                       -w01.y*(1.0f/7.0f) + w02.y*(12.0f/49.0f),
                       -w01.z*(1.0f/7.0f) + w02.z*(12.0f/49.0f),
                       -w01.w*(1.0f/7.0f) + w02.w*(12.0f/49.0f)};
        float b1[4] = {-w11.x*(1.0f/7.0f) + w12.x*(12.0f/49.0f),
                       -w11.y*(1.0f/7.0f) + w12.y*(12.0f/49.0f),
                       -w11.z*(1.0f/7.0f) + w12.z*(12.0f/49.0f),
                       -w11.w*(1.0f/7.0f) + w12.w*(12.0f/49.0f)};
        int dst = k2 * 128 + (cg ^ (8 * (k2 & 3)));
        uint4 ua = make_uint4(pack2h(a0[0], a1[0]), pack2h(a0[1], a1[1]),
                              pack2h(a0[2], a1[2]), pack2h(a0[3], a1[3]));
        uint4 ub = make_uint4(pack2h(b0[0], b1[0]), pack2h(b0[1], b1[1]),
                              pack2h(b0[2], b1[2]), pack2h(b0[3], b1[3]));
        *(uint4*)&Acs[dst] = ua;
        *(uint4*)&Bcs[dst] = ub;
    }

    const int c4 = t & 31;
    const float4 ga4 = *(const float4*)(gamma_ + 4 * c4);
    const float4 be4 = *(const float4*)(beta_  + 4 * c4);
    const float4 al4 = *(const float4*)(alpha_ + 4 * c4);

    const int d = t & 127, quarter = t >> 7;
    const float lw0 = linW[d], lw1 = linW[128 + d];
    const float lb = __ldg(linb);

    // main MMA: 16 warps as 4x4 grid over 256x128; q-MMA: warp w -> 8 cols
    const int m0 = (w >> 2) * 64, n0 = (w & 3) * 32, nq0 = w * 8;
    const int nIter = (E + 31) >> 5;

    __syncthreads();   // Acs/Bcs ready

    for (int it = blockIdx.x; it < nIter; it += gridDim.x) {
        const int ebase = it * 32;

        // warp w handles edges 2w, 2w+1; lane<16 loads member indices
        int mreg = 0;
        {
            int e = ebase + 2 * w + (lane >> 3);
            if (lane < 16 && e < E)
                mreg = __ldg(&members[e * 8 + (lane & 7)]);
        }

        // ---- stage A: gather + GraphNorm -> fp16 Gw / Sw (2 edges/warp) ----
#pragma unroll
        for (int ee = 0; ee < 2; ee++) {
            const int el = 2 * w + ee;
            const int e = ebase + el;
            unsigned* grow = Gw + el * 8 * 68 + 2 * c4;
            unsigned* srow = Sw + el * 68 + 2 * c4;
            if (e < E) {
                float4 xv[8];
#pragma unroll
                for (int i = 0; i < 8; i++) {
                    int node = __shfl_sync(0xffffffffu, mreg, ee * 8 + i);
                    xv[i] = *(const float4*)(g_x + (size_t)node * 128 + 4 * c4);
                }
                float4 mean = make_float4(0, 0, 0, 0);
#pragma unroll
                for (int i = 0; i < 8; i++) {
                    mean.x += xv[i].x; mean.y += xv[i].y;
                    mean.z += xv[i].z; mean.w += xv[i].w;
                }
                mean.x *= 0.125f; mean.y *= 0.125f;
                mean.z *= 0.125f; mean.w *= 0.125f;
                float4 am = make_float4(al4.x * mean.x, al4.y * mean.y,
                                        al4.z * mean.z, al4.w * mean.w);
                float4 var = make_float4(0, 0, 0, 0);
#pragma unroll
                for (int i = 0; i < 8; i++) {
                    xv[i].x -= am.x; xv[i].y -= am.y;
                    xv[i].z -= am.z; xv[i].w -= am.w;
                    var.x += xv[i].x * xv[i].x; var.y += xv[i].y * xv[i].y;
                    var.z += xv[i].z * xv[i].z; var.w += xv[i].w * xv[i].w;
                }
                float4 inv;
                inv.x = ga4.x * rsqrtf(var.x * 0.125f + EPSF);
                inv.y = ga4.y * rsqrtf(var.y * 0.125f + EPSF);
                inv.z = ga4.z * rsqrtf(var.z * 0.125f + EPSF);
                inv.w = ga4.w * rsqrtf(var.w * 0.125f + EPSF);
#pragma unroll
                for (int i = 0; i < 8; i++) {
                    uint2 u;
                    u.x = pack2h(xv[i].x * inv.x + be4.x, xv[i].y * inv.y + be4.y);
                    u.y = pack2h(xv[i].z * inv.z + be4.z, xv[i].w * inv.w + be4.w);
                    *(uint2*)(grow + i * 68) = u;
                }
                uint2 su;
                su.x = pack2h(inv.x * 8.0f * mean.x * (1.0f - al4.x) + 8.0f * be4.x,
                              inv.y * 8.0f * mean.y * (1.0f - al4.y) + 8.0f * be4.y);
                su.y = pack2h(inv.z * 8.0f * mean.z * (1.0f - al4.z) + 8.0f * be4.z,
                              inv.w * 8.0f * mean.w * (1.0f - al4.w) + 8.0f * be4.w);
                *(uint2*)srow = su;
            } else {
                uint2 z = make_uint2(0, 0);
#pragma unroll
                for (int i = 0; i < 8; i++) *(uint2*)(grow + i * 68) = z;
                *(uint2*)srow = z;
            }
        }
        __syncthreads();

        // ---- stage B: fp16 MMAs. main: g[256,128]@A ; q: S[32,128]@B ----
        float acc[4][4][4];
        float qac[2][4];
#pragma unroll
        for (int mf = 0; mf < 4; mf++)
#pragma unroll
            for (int nf = 0; nf < 4; nf++)
#pragma unroll
                for (int r = 0; r < 4; r++) acc[mf][nf][r] = 0.0f;
#pragma unroll
        for (int mf = 0; mf < 2; mf++)
#pragma unroll
            for (int r = 0; r < 4; r++) qac[mf][r] = 0.0f;

#pragma unroll
        for (int ks = 0; ks < 8; ks++) {
            const int k20 = ks * 8;
            const int sw = 8 * lk;
            unsigned b[4][2];
#pragma unroll
            for (int nf = 0; nf < 4; nf++) {
                int cb = n0 + nf * 8;
                b[nf][0] = Acs[(k20 + lk) * 128 + ((cb + lm) ^ sw)];
                b[nf][1] = Acs[(k20 + lk + 4) * 128 + ((cb + lm) ^ sw)];
            }
#pragma unroll
            for (int mf = 0; mf < 4; mf++) {
                int rb = m0 + mf * 16;
                unsigned a0 = Gw[(rb + lm) * 68 + k20 + lk];
                unsigned a1 = Gw[(rb + lm + 8) * 68 + k20 + lk];
                unsigned a2 = Gw[(rb + lm) * 68 + k20 + lk + 4];
                unsigned a3 = Gw[(rb + lm + 8) * 68 + k20 + lk + 4];
#pragma unroll
                for (int nf = 0; nf < 4; nf++)
                    mma16h(acc[mf][nf], a0, a1, a2, a3, b[nf][0], b[nf][1]);
            }
            unsigned qb0 = Bcs[(k20 + lk) * 128 + ((nq0 + lm) ^ sw)];
            unsigned qb1 = Bcs[(k20 + lk + 4) * 128 + ((nq0 + lm) ^ sw)];
#pragma unroll
            for (int mf = 0; mf < 2; mf++) {
                int rb = mf * 16;
                unsigned s0 = Sw[(rb + lm) * 68 + k20 + lk];
                unsigned s1 = Sw[(rb + lm + 8) * 68 + k20 + lk];
                unsigned s2 = Sw[(rb + lm) * 68 + k20 + lk + 4];
                unsigned s3 = Sw[(rb + lm + 8) * 68 + k20 + lk + 4];
                mma16h(qac[mf], s0, s1, s2, s3, qb0, qb1);
            }
        }
        // all Sw reads complete before Qsm overwrites the same region
        __syncthreads();
        {
            int c = nq0 + 2 * lk;
            float cb0 = __ldg(chebb + c), cb1 = __ldg(chebb + c + 1);
#pragma unroll
            for (int mf = 0; mf < 2; mf++) {
                int rb = mf * 16;
                Qsm[(rb + lm) * 136 + c]           = qac[mf][0] + cb0;
                Qsm[(rb + lm) * 136 + c + 1]       = qac[mf][1] + cb1;
                Qsm[(rb + lm + 8) * 136 + c]       = qac[mf][2] + cb0;
                Qsm[(rb + lm + 8) * 136 + c + 1]   = qac[mf][3] + cb1;
            }
        }
        __syncthreads();

        // ---- stage C: h = clip(acc + Q[e][c]) -> Hs (reuses Gw space) ----
#pragma unroll
        for (int mf = 0; mf < 4; mf++) {
            int rb = m0 + mf * 16 + lm;
            int e0 = rb >> 3;
            int e1 = (rb + 8) >> 3;
#pragma unroll
            for (int nf = 0; nf < 4; nf++) {
                int c = n0 + nf * 8 + 2 * lk;
                float2 q0 = *(const float2*)&Qsm[e0 * 136 + c];
                float2 q1 = *(const float2*)&Qsm[e1 * 136 + c];
                float2 v0, v1;
                v0.x = clipf(acc[mf][nf][0] + q0.x);
                v0.y = clipf(acc[mf][nf][1] + q0.y);
                v1.x = clipf(acc[mf][nf][2] + q1.x);
                v1.y = clipf(acc[mf][nf][3] + q1.y);
                *(float2*)&Hs[rb * 136 + c]       = v0;
                *(float2*)&Hs[(rb + 8) * 136 + c] = v1;
            }
        }
        __syncthreads();

        // ---- stage D: pooling + linear head + sigmoid (8 edges / thread) ----
#pragma unroll
        for (int j = 0; j < 8; j++) {
            int elj = quarter * 8 + j;
            float mx = -2.0f, mn = 2.0f, ss = 0.0f;
#pragma unroll
            for (int i = 0; i < 8; i++) {
                float h = Hs[(elj * 8 + i) * 136 + d];
                mx = fmaxf(mx, h);
                mn = fminf(mn, h);
                ss += h * h;
            }
            float v = (mx - mn) * lw0 + sqrtf(ss * 0.125f) * lw1;
            v += __shfl_xor_sync(0xffffffffu, v, 16);
            v += __shfl_xor_sync(0xffffffffu, v, 8);
            v += __shfl_xor_sync(0xffffffffu, v, 4);
            v += __shfl_xor_sync(0xffffffffu, v, 2);
            v += __shfl_xor_sync(0xffffffffu, v, 1);
            if (lane == 0) red[elj * 4 + (w & 3)] = v;
        }
        __syncthreads();
        if (t < 32) {
            int eo = ebase + t;
            if (eo < E) {
                float* r = red + t * 4;
                float logit = r[0] + r[1] + r[2] + r[3] + lb;
                out[eo] = 1.0f / (1.0f + expf(-logit));
            }
        }
        __syncthreads();   // protect smem before next iteration
    }
}

// ---------------------------------------------------------------------------
extern "C" void kernel_launch(void* const* d_in, const int* in_sizes, int n_in,
                              void* d_out, int out_size) {
    const float* pos   = (const float*)d_in[0];
    const float* Wenc  = (const float*)d_in[1];
    const float* benc  = (const float*)d_in[2];
    const float* gam   = (const float*)d_in[3];
    const float* bet   = (const float*)d_in[4];
    const float* alp   = (const float*)d_in[5];
    const float* chebW = (const float*)d_in[6];
    const float* chebb = (const float*)d_in[7];
    const float* linW  = (const float*)d_in[8];
    const float* linb  = (const float*)d_in[9];
    const int*   membs = (const int*)d_in[10];

    int N = in_sizes[0] / FDIM;   // 50000
    int E = in_sizes[10] / 8;     // 20000

    cudaFuncSetAttribute(encoder_cp, cudaFuncAttributeMaxDynamicSharedMemorySize,
                         ENC_SMEM);
    encoder_cp<<<(N + 127) / 128, 256, ENC_SMEM>>>(pos, Wenc, benc, N);

    cudaFuncSetAttribute(edge_mma, cudaFuncAttributeMaxDynamicSharedMemorySize,
                         ESMEM);
    int nIter = (E + 31) / 32;
    int grid = nIter < 148 ? nIter : 148;
    edge_mma<<<grid, 512, ESMEM>>>(membs, chebW, gam, bet, alp, chebb, linW,
                                   linb, (float*)d_out, E);
}

// round 10
// speedup vs baseline: 1.1138x; 1.0024x over previous
#include <cuda_runtime.h>
#include <cuda_fp16.h>
#include <math.h>
#include <stdint.h>

#define FDIM 512
#define DDIM 128
#define NMAX 50048
#define EPSF 1e-5f

// Scratch (allocation-free rule: device globals)
__device__ float g_x[(size_t)NMAX * DDIM];      // encoded node features

__device__ __forceinline__ unsigned f2tf(float x) {
    unsigned r; asm("cvt.rna.tf32.f32 %0, %1;" : "=r"(r) : "f"(x)); return r;
}
__device__ __forceinline__ void mma8(float* c, unsigned a0, unsigned a1,
                                     unsigned a2, unsigned a3,
                                     unsigned b0, unsigned b1) {
    asm volatile(
        "mma.sync.aligned.m16n8k8.row.col.f32.tf32.tf32.f32 "
        "{%0,%1,%2,%3},{%4,%5,%6,%7},{%8,%9},{%0,%1,%2,%3};"
        : "+f"(c[0]), "+f"(c[1]), "+f"(c[2]), "+f"(c[3])
        : "r"(a0), "r"(a1), "r"(a2), "r"(a3), "r"(b0), "r"(b1));
}
__device__ __forceinline__ void mma16h(float* c, unsigned a0, unsigned a1,
                                       unsigned a2, unsigned a3,
                                       unsigned b0, unsigned b1) {
    asm volatile(
        "mma.sync.aligned.m16n8k16.row.col.f32.f16.f16.f32 "
        "{%0,%1,%2,%3},{%4,%5,%6,%7},{%8,%9},{%0,%1,%2,%3};"
        : "+f"(c[0]), "+f"(c[1]), "+f"(c[2]), "+f"(c[3])
        : "r"(a0), "r"(a1), "r"(a2), "r"(a3), "r"(b0), "r"(b1));
}
__device__ __forceinline__ float clipf(float v) {
    return fminf(1.0f, fmaxf(-1.0f, v));
}
__device__ __forceinline__ unsigned pack2h(float lo, float hi) {
    __half2 h = __floats2half2_rn(lo, hi);
    return *(unsigned*)&h;
}
__device__ __forceinline__ uint32_t smem_u32(const void* p) {
    uint32_t a;
    asm("{ .reg .u64 t; cvta.to.shared.u64 t, %1; cvt.u32.u64 %0, t; }"
        : "=r"(a) : "l"(p));
    return a;
}
__device__ __forceinline__ void cpasync16(uint32_t dst, const void* src, int szr) {
    asm volatile("cp.async.ca.shared.global [%0], [%1], 16, %2;"
                 :: "r"(dst), "l"(src), "r"(szr) : "memory");
}
#define CP_COMMIT() asm volatile("cp.async.commit_group;" ::: "memory")
#define CP_WAIT1()  asm volatile("cp.async.wait_group 1;" ::: "memory")

// ---------------------------------------------------------------------------
// Kernel 1: encoder  x = clip(pos @ W_enc + b, -1, 1) via tf32 mma.sync.
// (UNCHANGED — known good ~52us; controlled experiment on edge kernel)
// ---------------------------------------------------------------------------
#define ENC_A_BYTES (128 * 20 * 4)                    // 10240
#define ENC_B_BYTES (16 * 128 * 4)                    // 8192
#define ENC_SMEM    (3 * (ENC_A_BYTES + ENC_B_BYTES)) // 55296

__global__ __launch_bounds__(256, 2)
void encoder_cp(const float* __restrict__ pos, const float* __restrict__ W,
                const float* __restrict__ bias, int N) {
    extern __shared__ unsigned char sm[];
    const uint32_t smb = smem_u32(sm);

    const int t = threadIdx.x, lane = t & 31, w = t >> 5;
    const int wy = w >> 1, wx = w & 1;
    const int lm = lane >> 2, lk = lane & 3;
    const int m0 = blockIdx.x * 128;

    const int ar0 = t >> 2, akq = t & 3;
    const int bk0 = t >> 5, bnq = t & 31;

    float acc[2][8][4];
#pragma unroll
    for (int mf = 0; mf < 2; mf++)
#pragma unroll
        for (int nf = 0; nf < 8; nf++)
#pragma unroll
            for (int r = 0; r < 4; r++) acc[mf][nf][r] = 0.0f;

    auto issue = [&](int s, int kt) {
        const uint32_t abase = smb + s * ENC_A_BYTES;
        const uint32_t bbase = smb + 3 * ENC_A_BYTES + s * ENC_B_BYTES;
#pragma unroll
        for (int h = 0; h < 2; h++) {
            int r = ar0 + h * 64;
            const float* src = pos + (size_t)(m0 + r) * FDIM + kt * 16 + akq * 4;
            uint32_t dst = abase + (r * 20 + akq * 4) * 4;
            cpasync16(dst, src, (m0 + r) < N ? 16 : 0);
        }
#pragma unroll
        for (int h = 0; h < 2; h++) {
            int k = bk0 + h * 8;
            const float* src = W + (size_t)(kt * 16 + k) * 128 + bnq * 4;
            uint32_t dst = bbase + (k * 128 + ((bnq * 4) ^ (8 * (k & 3)))) * 4;
            cpasync16(dst, src, 16);
        }
    };

    issue(0, 0); CP_COMMIT();
    issue(1, 1); CP_COMMIT();

    for (int kt = 0; kt < 32; kt++) {
        const int s = kt % 3;
        CP_WAIT1();
        __syncthreads();
        if (kt + 2 < 32) issue((kt + 2) % 3, kt + 2);
        CP_COMMIT();

        const unsigned* As = (const unsigned*)(sm + s * ENC_A_BYTES);
        const unsigned* Bs = (const unsigned*)(sm + 3 * ENC_A_BYTES + s * ENC_B_BYTES);
#pragma unroll
        for (int kh = 0; kh < 2; kh++) {
            const int k0 = kh * 8;
            unsigned a[2][4], b[8][2];
#pragma unroll
            for (int mf = 0; mf < 2; mf++) {
                int rb = wy * 32 + mf * 16;
                a[mf][0] = As[(rb + lm) * 20 + k0 + lk];
                a[mf][1] = As[(rb + lm + 8) * 20 + k0 + lk];
                a[mf][2] = As[(rb + lm) * 20 + k0 + lk + 4];
                a[mf][3] = As[(rb + lm + 8) * 20 + k0 + lk + 4];
            }
#pragma unroll
            for (int nf = 0; nf < 8; nf++) {
                int cb = wx * 64 + nf * 8;
                b[nf][0] = Bs[(k0 + lk) * 128 + ((cb + lm) ^ (8 * lk))];
                b[nf][1] = Bs[(k0 + lk + 4) * 128 + ((cb + lm) ^ (8 * lk))];
            }
#pragma unroll
            for (int mf = 0; mf < 2; mf++)
#pragma unroll
                for (int nf = 0; nf < 8; nf++)
                    mma8(acc[mf][nf], a[mf][0], a[mf][1], a[mf][2], a[mf][3],
                         b[nf][0], b[nf][1]);
        }
    }

#pragma unroll
    for (int mf = 0; mf < 2; mf++) {
        int r0 = m0 + wy * 32 + mf * 16 + lm;
#pragma unroll
        for (int nf = 0; nf < 8; nf++) {
            int c = wx * 64 + nf * 8 + 2 * lk;
            float b0 = __ldg(bias + c), b1 = __ldg(bias + c + 1);
            if (r0 < N) {
                float2 v;
                v.x = clipf(acc[mf][nf][0] + b0);
                v.y = clipf(acc[mf][nf][1] + b1);
                *(float2*)&g_x[(size_t)r0 * 128 + c] = v;
            }
            if (r0 + 8 < N) {
                float2 v;
                v.x = clipf(acc[mf][nf][2] + b0);
                v.y = clipf(acc[mf][nf][3] + b1);
                *(float2*)&g_x[(size_t)(r0 + 8) * 128 + c] = v;
            }
        }
    }
}

// ---------------------------------------------------------------------------
// Kernel 2: fused per-hyperedge pipeline, 8 edges/iter, FP16 mma m16n8k16.
// R10: 256 threads + 113.5KB smem -> 2 CTAs/SM (two independent barrier
// domains overlap; per-thread work identical to R7).
// smem layout (dynamic, 113536 B):
//   Acs  word[64*128] @0       : Cheb A fp16, [k2][n] XOR-8(k2&3) swizzle
//   Bcs  word[64*128] @32768   : Cheb B fp16
//   Gw   word[64*68]  @65536   : g fp16, [row][k2], stride 68 words
//   Hs   float[64*136]@65536   : (union w/ Gw) h fp32, stride 136
//   Sw   word[16*68]  @100352  : S fp16 (rows 8-15 zero)
//   Qsm  float[16*136]@104704  : q = S@B + chebb
//   red  float[8*4]   @113408
// ---------------------------------------------------------------------------
#define ESMEM 113536

__global__ __launch_bounds__(256, 2)
void edge_mma(const int* __restrict__ members, const float* __restrict__ chebW,
              const float* __restrict__ gamma_, const float* __restrict__ beta_,
              const float* __restrict__ alpha_, const float* __restrict__ chebb,
              const float* __restrict__ linW, const float* __restrict__ linb,
              float* __restrict__ out, int E) {
    extern __shared__ unsigned char esm[];
    unsigned* Acs = (unsigned*)esm;
    unsigned* Bcs = (unsigned*)(esm + 32768);
    unsigned* Gw  = (unsigned*)(esm + 65536);
    float*    Hs  = (float*)(esm + 65536);
    unsigned* Sw  = (unsigned*)(esm + 100352);
    float*    Qsm = (float*)(esm + 104704);
    float*    red = (float*)(esm + 113408);

    const int t = threadIdx.x;
    const int lane = t & 31, w = t >> 5;
    const int lm = lane >> 2, lk = lane & 3;

    // ---- fold of prep: A = W0 + W1/7 - 47/49 W2 ; B = -W1/7 + 12/49 W2 ----
    for (int i = t; i < 2048; i += 256) {
        int k2 = i >> 5;
        int cg = (i & 31) * 4;
        const float* p0 = chebW + (2 * k2) * 128 + cg;
        const float* p1 = p0 + 128;
        float4 w00 = __ldg((const float4*)(p0));
        float4 w01 = __ldg((const float4*)(p0 + 16384));
        float4 w02 = __ldg((const float4*)(p0 + 32768));
        float4 w10 = __ldg((const float4*)(p1));
        float4 w11 = __ldg((const float4*)(p1 + 16384));
        float4 w12 = __ldg((const float4*)(p1 + 32768));
        float a0[4] = {w00.x + w01.x*(1.0f/7.0f) - w02.x*(47.0f/49.0f),
                       w00.y + w01.y*(1.0f/7.0f) - w02.y*(47.0f/49.0f),
                       w00.z + w01.z*(1.0f/7.0f) - w02.z*(47.0f/49.0f),
                       w00.w + w01.w*(1.0f/7.0f) - w02.w*(47.0f/49.0f)};
        float a1[4] = {w10.x + w11.x*(1.0f/7.0f) - w12.x*(47.0f/49.0f),
                       w10.y + w11.y*(1.0f/7.0f) - w12.y*(47.0f/49.0f),
                       w10.z + w11.z*(1.0f/7.0f) - w12.z*(47.0f/49.0f),
                       w10.w + w11.w*(1.0f/7.0f) - w12.w*(47.0f/49.0f)};
        float b0[4] = {-w01.x*(1.0f/7.0f) + w02.x*(12.0f/49.0f),
                       -w01.y*(1.0f/7.0f) + w02.y*(12.0f/49.0f),
                       -w01.z*(1.0f/7.0f) + w02.z*(12.0f/49.0f),
                       -w01.w*(1.0f/7.0f) + w02.w*(12.0f/49.0f)};
        float b1[4] = {-w11.x*(1.0f/7.0f) + w12.x*(12.0f/49.0f),
                       -w11.y*(1.0f/7.0f) + w12.y*(12.0f/49.0f),
                       -w11.z*(1.0f/7.0f) + w12.z*(12.0f/49.0f),
                       -w11.w*(1.0f/7.0f) + w12.w*(12.0f/49.0f)};
        int dst = k2 * 128 + (cg ^ (8 * (k2 & 3)));
        uint4 ua = make_uint4(pack2h(a0[0], a1[0]), pack2h(a0[1], a1[1]),
                              pack2h(a0[2], a1[2]), pack2h(a0[3], a1[3]));
        uint4 ub = make_uint4(pack2h(b0[0], b1[0]), pack2h(b0[1], b1[1]),
                              pack2h(b0[2], b1[2]), pack2h(b0[3], b1[3]));
        *(uint4*)&Acs[dst] = ua;
        *(uint4*)&Bcs[dst] = ub;
    }
    // zero Sw rows 8-15 (never written; q-MMA reads them as zero padding)
    for (int i = t; i < 544; i += 256) Sw[544 + i] = 0u;

    // stage A mapping: warp w = edge w; channels 4*lane
    const int c4 = lane;
    const float4 ga4 = *(const float4*)(gamma_ + 4 * c4);
    const float4 be4 = *(const float4*)(beta_  + 4 * c4);
    const float4 al4 = *(const float4*)(alpha_ + 4 * c4);

    // stage D mapping: d = channel, pair = edge group (0: edges 0-3, 1: 4-7)
    const int d = t & 127, pair = t >> 7;
    const float lw0 = linW[d], lw1 = linW[128 + d];
    const float lb = __ldg(linb);

    // MMA mapping: 8 warps as 2x4 over 64x128; q-MMA: warp w -> 16 cols
    const int m0 = (w >> 2) * 32, n0 = (w & 3) * 32, nq0 = w * 16;
    const int nIter = (E + 7) >> 3;

    __syncthreads();   // Acs/Bcs/Sw-zeros ready

    for (int it = blockIdx.x; it < nIter; it += gridDim.x) {
        const int ebase = it * 8;

        const int el = w;
        const int e = ebase + el;
        int mreg = 0;
        if (lane < 8 && e < E) mreg = __ldg(&members[e * 8 + lane]);

        // ---- stage A: gather + GraphNorm -> fp16 Gw / Sw (1 edge/warp) ----
        {
            unsigned* grow = Gw + el * 8 * 68 + 2 * c4;
            unsigned* srow = Sw + el * 68 + 2 * c4;
            if (e < E) {
                float4 xv[8];
#pragma unroll
                for (int i = 0; i < 8; i++) {
                    int node = __shfl_sync(0xffffffffu, mreg, i);
                    xv[i] = *(const float4*)(g_x + (size_t)node * 128 + 4 * c4);
                }
                float4 mean = make_float4(0, 0, 0, 0);
#pragma unroll
                for (int i = 0; i < 8; i++) {
                    mean.x += xv[i].x; mean.y += xv[i].y;
                    mean.z += xv[i].z; mean.w += xv[i].w;
                }
                mean.x *= 0.125f; mean.y *= 0.125f;
                mean.z *= 0.125f; mean.w *= 0.125f;
                float4 am = make_float4(al4.x * mean.x, al4.y * mean.y,
                                        al4.z * mean.z, al4.w * mean.w);
                float4 var = make_float4(0, 0, 0, 0);
#pragma unroll
                for (int i = 0; i < 8; i++) {
                    xv[i].x -= am.x; xv[i].y -= am.y;
                    xv[i].z -= am.z; xv[i].w -= am.w;
                    var.x += xv[i].x * xv[i].x; var.y += xv[i].y * xv[i].y;
                    var.z += xv[i].z * xv[i].z; var.w += xv[i].w * xv[i].w;
                }
                float4 inv;
                inv.x = ga4.x * rsqrtf(var.x * 0.125f + EPSF);
                inv.y = ga4.y * rsqrtf(var.y * 0.125f + EPSF);
                inv.z = ga4.z * rsqrtf(var.z * 0.125f + EPSF);
                inv.w = ga4.w * rsqrtf(var.w * 0.125f + EPSF);
#pragma unroll
                for (int i = 0; i < 8; i++) {
                    uint2 u;
                    u.x = pack2h(xv[i].x * inv.x + be4.x, xv[i].y * inv.y + be4.y);
                    u.y = pack2h(xv[i].z * inv.z + be4.z, xv[i].w * inv.w + be4.w);
                    *(uint2*)(grow + i * 68) = u;
                }
                uint2 su;
                su.x = pack2h(inv.x * 8.0f * mean.x * (1.0f - al4.x) + 8.0f * be4.x,
                              inv.y * 8.0f * mean.y * (1.0f - al4.y) + 8.0f * be4.y);
                su.y = pack2h(inv.z * 8.0f * mean.z * (1.0f - al4.z) + 8.0f * be4.z,
                              inv.w * 8.0f * mean.w * (1.0f - al4.w) + 8.0f * be4.w);
                *(uint2*)srow = su;
            } else {
                uint2 z = make_uint2(0, 0);
#pragma unroll
                for (int i = 0; i < 8; i++) *(uint2*)(grow + i * 68) = z;
                *(uint2*)srow = z;
            }
        }
        __syncthreads();

        // ---- stage B: fp16 MMAs. main: g[64,128]@A ; q: S[16,128]@B ----
        float acc[2][4][4];
        float qac[2][4];
#pragma unroll
        for (int mf = 0; mf < 2; mf++)
#pragma unroll
            for (int nf = 0; nf < 4; nf++)
#pragma unroll
                for (int r = 0; r < 4; r++) acc[mf][nf][r] = 0.0f;
#pragma unroll
        for (int nf = 0; nf < 2; nf++)
#pragma unroll
            for (int r = 0; r < 4; r++) qac[nf][r] = 0.0f;

#pragma unroll
        for (int ks = 0; ks < 8; ks++) {
            const int k20 = ks * 8;
            const int sw = 8 * lk;
            unsigned a[2][4];
#pragma unroll
            for (int mf = 0; mf < 2; mf++) {
                int rb = m0 + mf * 16;
                a[mf][0] = Gw[(rb + lm) * 68 + k20 + lk];
                a[mf][1] = Gw[(rb + lm + 8) * 68 + k20 + lk];
                a[mf][2] = Gw[(rb + lm) * 68 + k20 + lk + 4];
                a[mf][3] = Gw[(rb + lm + 8) * 68 + k20 + lk + 4];
            }
            unsigned b[4][2];
#pragma unroll
            for (int nf = 0; nf < 4; nf++) {
                int cb = n0 + nf * 8;
                b[nf][0] = Acs[(k20 + lk) * 128 + ((cb + lm) ^ sw)];
                b[nf][1] = Acs[(k20 + lk + 4) * 128 + ((cb + lm) ^ sw)];
            }
#pragma unroll
            for (int mf = 0; mf < 2; mf++)
#pragma unroll
                for (int nf = 0; nf < 4; nf++)
                    mma16h(acc[mf][nf], a[mf][0], a[mf][1], a[mf][2], a[mf][3],
                           b[nf][0], b[nf][1]);
            unsigned sa0 = Sw[lm * 68 + k20 + lk];
            unsigned sa1 = Sw[(lm + 8) * 68 + k20 + lk];
            unsigned sa2 = Sw[lm * 68 + k20 + lk + 4];
            unsigned sa3 = Sw[(lm + 8) * 68 + k20 + lk + 4];
#pragma unroll
            for (int nf = 0; nf < 2; nf++) {
                int cb = nq0 + nf * 8;
                unsigned qb0 = Bcs[(k20 + lk) * 128 + ((cb + lm) ^ sw)];
                unsigned qb1 = Bcs[(k20 + lk + 4) * 128 + ((cb + lm) ^ sw)];
                mma16h(qac[nf], sa0, sa1, sa2, sa3, qb0, qb1);
            }
        }
        // write Qsm (+chebb folded in); rows 8-15 are padding (unused)
#pragma unroll
        for (int nf = 0; nf < 2; nf++) {
            int c = nq0 + nf * 8 + 2 * lk;
            float cb0 = __ldg(chebb + c), cb1 = __ldg(chebb + c + 1);
            Qsm[lm * 136 + c]           = qac[nf][0] + cb0;
            Qsm[lm * 136 + c + 1]       = qac[nf][1] + cb1;
            Qsm[(lm + 8) * 136 + c]     = qac[nf][2] + cb0;
            Qsm[(lm + 8) * 136 + c + 1] = qac[nf][3] + cb1;
        }
        __syncthreads();

        // ---- stage C: h = clip(acc + Q[e][c]) -> Hs (reuses Gw space) ----
#pragma unroll
        for (int mf = 0; mf < 2; mf++) {
            int rb = m0 + mf * 16 + lm;
            int e0 = rb >> 3;
            int e1 = (rb + 8) >> 3;
#pragma unroll
            for (int nf = 0; nf < 4; nf++) {
                int c = n0 + nf * 8 + 2 * lk;
                float2 q0 = *(const float2*)&Qsm[e0 * 136 + c];
                float2 q1 = *(const float2*)&Qsm[e1 * 136 + c];
                float2 v0, v1;
                v0.x = clipf(acc[mf][nf][0] + q0.x);
                v0.y = clipf(acc[mf][nf][1] + q0.y);
                v1.x = clipf(acc[mf][nf][2] + q1.x);
                v1.y = clipf(acc[mf][nf][3] + q1.y);
                *(float2*)&Hs[rb * 136 + c]       = v0;
                *(float2*)&Hs[(rb + 8) * 136 + c] = v1;
            }
        }
        __syncthreads();

        // ---- stage D: pooling + linear head + sigmoid (4 edges / thread) ----
#pragma unroll
        for (int j = 0; j < 4; j++) {
            int elj = pair * 4 + j;
            float mx = -2.0f, mn = 2.0f, ss = 0.0f;
#pragma unroll
            for (int i = 0; i < 8; i++) {
                float h = Hs[(elj * 8 + i) * 136 + d];
                mx = fmaxf(mx, h);
                mn = fminf(mn, h);
                ss += h * h;
            }
            float v = (mx - mn) * lw0 + sqrtf(ss * 0.125f) * lw1;
            v += __shfl_xor_sync(0xffffffffu, v, 16);
            v += __shfl_xor_sync(0xffffffffu, v, 8);
            v += __shfl_xor_sync(0xffffffffu, v, 4);
            v += __shfl_xor_sync(0xffffffffu, v, 2);
            v += __shfl_xor_sync(0xffffffffu, v, 1);
            if (lane == 0) red[elj * 4 + (w & 3)] = v;
        }
        __syncthreads();
        if (t < 8) {
            int eo = ebase + t;
            if (eo < E) {
                float* r = red + t * 4;
                float logit = r[0] + r[1] + r[2] + r[3] + lb;
                out[eo] = 1.0f / (1.0f + expf(-logit));
            }
        }
        __syncthreads();   // protect smem before next iteration
    }
}

// ---------------------------------------------------------------------------
extern "C" void kernel_launch(void* const* d_in, const int* in_sizes, int n_in,
                              void* d_out, int out_size) {
    const float* pos   = (const float*)d_in[0];
    const float* Wenc  = (const float*)d_in[1];
    const float* benc  = (const float*)d_in[2];
    const float* gam   = (const float*)d_in[3];
    const float* bet   = (const float*)d_in[4];
    const float* alp   = (const float*)d_in[5];
    const float* chebW = (const float*)d_in[6];
    const float* chebb = (const float*)d_in[7];
    const float* linW  = (const float*)d_in[8];
    const float* linb  = (const float*)d_in[9];
    const int*   membs = (const int*)d_in[10];

    int N = in_sizes[0] / FDIM;   // 50000
    int E = in_sizes[10] / 8;     // 20000

    cudaFuncSetAttribute(encoder_cp, cudaFuncAttributeMaxDynamicSharedMemorySize,
                         ENC_SMEM);
    encoder_cp<<<(N + 127) / 128, 256, ENC_SMEM>>>(pos, Wenc, benc, N);

    cudaFuncSetAttribute(edge_mma, cudaFuncAttributeMaxDynamicSharedMemorySize,
                         ESMEM);
    int nIter = (E + 7) / 8;
    int grid = nIter < 296 ? nIter : 296;   // 2 CTAs per SM
    edge_mma<<<grid, 256, ESMEM>>>(membs, chebW, gam, bet, alp, chebb, linW,
                                   linb, (float*)d_out, E);
}

// round 12
// speedup vs baseline: 1.2175x; 1.0931x over previous
#include <cuda_runtime.h>
#include <cuda_fp16.h>
#include <math.h>
#include <stdint.h>

#define FDIM 512
#define DDIM 128
#define NMAX 50048
#define EPSF 1e-5f

// Scratch (allocation-free rule: device globals)
__device__ float g_x[(size_t)NMAX * DDIM];      // encoded node features
__device__ unsigned g_Wh[256 * 128];            // W_enc fp16, word = k-pair, [k2][n]

__device__ __forceinline__ void mma16h(float* c, unsigned a0, unsigned a1,
                                       unsigned a2, unsigned a3,
                                       unsigned b0, unsigned b1) {
    asm volatile(
        "mma.sync.aligned.m16n8k16.row.col.f32.f16.f16.f32 "
        "{%0,%1,%2,%3},{%4,%5,%6,%7},{%8,%9},{%0,%1,%2,%3};"
        : "+f"(c[0]), "+f"(c[1]), "+f"(c[2]), "+f"(c[3])
        : "r"(a0), "r"(a1), "r"(a2), "r"(a3), "r"(b0), "r"(b1));
}
__device__ __forceinline__ float clipf(float v) {
    return fminf(1.0f, fmaxf(-1.0f, v));
}
__device__ __forceinline__ unsigned pack2h(float lo, float hi) {
    __half2 h = __floats2half2_rn(lo, hi);
    return *(unsigned*)&h;
}
__device__ __forceinline__ uint32_t smem_u32(const void* p) {
    uint32_t a;
    asm("{ .reg .u64 t; cvta.to.shared.u64 t, %1; cvt.u32.u64 %0, t; }"
        : "=r"(a) : "l"(p));
    return a;
}
__device__ __forceinline__ void cpasync16(uint32_t dst, const void* src, int szr) {
    asm volatile("cp.async.ca.shared.global [%0], [%1], 16, %2;"
                 :: "r"(dst), "l"(src), "r"(szr) : "memory");
}
#define CP_COMMIT() asm volatile("cp.async.commit_group;" ::: "memory")
#define CP_WAIT1()  asm volatile("cp.async.wait_group 1;" ::: "memory")

// ---------------------------------------------------------------------------
// Kernel 0: pack W_enc to fp16 k-pair words over ALL K=512 (256 k2-rows):
//   g_Wh[k2*128+n] = (W[2k2][n], W[2k2+1][n])
// ---------------------------------------------------------------------------
__global__ void prep_w(const float* __restrict__ W) {
    int i = blockIdx.x * blockDim.x + threadIdx.x;
    if (i < 256 * 128) {
        int k2 = i >> 7, n = i & 127;
        g_Wh[i] = pack2h(W[2 * k2 * 128 + n], W[(2 * k2 + 1) * 128 + n]);
    }
}

// ---------------------------------------------------------------------------
// Kernel 1: encoder x = clip(pos @ W_enc + b, -1, 1) via FP16 mma m16n8k16.
// 512 threads, tile 128x128, BK=32, 16 warps (4x4), warp tile 32x32.
// B (W fp16): cp.async 3-stage from g_Wh. A (pos): LDG fp32 with depth-4
// register prefetch -> pack fp16 -> STS, 3 smem stages. 1 barrier / k-tile.
// As: [row][k2] stride 20 words; Bs: [k2][n] word-swizzle n^(8*(k2&3)).
// smem: As 3x10240B @0 ; Bs 3x8192B @30720 ; total 55296B.
// ---------------------------------------------------------------------------
#define ENC_SMEM 55296

__global__ __launch_bounds__(512, 1)
void encoder_h2(const float* __restrict__ pos, const float* __restrict__ bias,
                int N) {
    extern __shared__ unsigned char sm[];
    unsigned* As = (unsigned*)sm;                 // 3 stages x 2560 words
    unsigned* Bs = (unsigned*)(sm + 30720);       // 3 stages x 2048 words
    const uint32_t smb = smem_u32(sm);

    const int t = threadIdx.x, lane = t & 31, w = t >> 5;
    const int lm = lane >> 2, lk = lane & 3;
    const int m0 = (w >> 2) * 32, n0 = (w & 3) * 32;
    const int m0g = blockIdx.x * 128;

    // A staging: thread -> (row, k-quad of 8 floats)
    const int arow = t >> 2, aq = t & 3;
    const bool aok = (m0g + arow) < N;
    const float* ap = pos + (size_t)(m0g + arow) * FDIM + aq * 8;
    const int asoff = arow * 20 + aq * 4;
    // B staging: thread -> (k2 row, 4-word col group)
    const int bk2 = t >> 5, bn4 = (t & 31) * 4;
    const uint32_t bdst = smb + 30720 + (bk2 * 128 + (bn4 ^ (8 * (bk2 & 3)))) * 4;
    const unsigned* bsrc = g_Wh + bk2 * 128 + bn4;

    float acc[2][4][4];
#pragma unroll
    for (int mf = 0; mf < 2; mf++)
#pragma unroll
        for (int nf = 0; nf < 4; nf++)
#pragma unroll
            for (int r = 0; r < 4; r++) acc[mf][nf][r] = 0.0f;

    float4 rb0[2], rb1[2];
    auto ldgA = [&](float4* r, int kt) {
        if (aok) {
            r[0] = *(const float4*)(ap + kt * 32);
            r[1] = *(const float4*)(ap + kt * 32 + 4);
        } else {
            r[0] = make_float4(0, 0, 0, 0);
            r[1] = make_float4(0, 0, 0, 0);
        }
    };
    auto stsA = [&](int s, const float4* r) {
        uint4 u = make_uint4(pack2h(r[0].x, r[0].y), pack2h(r[0].z, r[0].w),
                             pack2h(r[1].x, r[1].y), pack2h(r[1].z, r[1].w));
        *(uint4*)&As[s * 2560 + asoff] = u;
    };
    auto cpB = [&](int s, int kt) {
        cpasync16(bdst + s * 8192, bsrc + kt * 16 * 128, 16);
    };

    // prologue: tiles 0,1 staged; tiles 2,3 in registers
    ldgA(rb0, 0); ldgA(rb1, 1);
    cpB(0, 0); CP_COMMIT();
    cpB(1, 1); CP_COMMIT();
    stsA(0, rb0); stsA(1, rb1);
    ldgA(rb0, 2); ldgA(rb1, 3);

    for (int kt = 0; kt < 16; kt++) {
        const int s = kt % 3;
        CP_WAIT1();             // B(kt) landed (groups complete in order)
        __syncthreads();        // everyone done MMA(kt-1); A(kt) visible
        if (kt + 2 < 16) {
            float4* rb = (kt & 1) ? rb1 : rb0;
            stsA((kt + 2) % 3, rb);
            cpB((kt + 2) % 3, kt + 2);
            if (kt + 4 < 16) ldgA(rb, kt + 4);
        }
        CP_COMMIT();            // empty group when nothing issued keeps order

        const unsigned* Asp = As + s * 2560;
        const unsigned* Bsp = Bs + s * 2048;
#pragma unroll
        for (int ks = 0; ks < 2; ks++) {
            const int k20 = ks * 8;
            const int sw = 8 * lk;
            unsigned a[2][4];
#pragma unroll
            for (int mf = 0; mf < 2; mf++) {
                int rb_ = m0 + mf * 16;
                a[mf][0] = Asp[(rb_ + lm) * 20 + k20 + lk];
                a[mf][1] = Asp[(rb_ + lm + 8) * 20 + k20 + lk];
                a[mf][2] = Asp[(rb_ + lm) * 20 + k20 + lk + 4];
                a[mf][3] = Asp[(rb_ + lm + 8) * 20 + k20 + lk + 4];
            }
            unsigned b[4][2];
#pragma unroll
            for (int nf = 0; nf < 4; nf++) {
                int cb = n0 + nf * 8;
                b[nf][0] = Bsp[(k20 + lk) * 128 + ((cb + lm) ^ sw)];
                b[nf][1] = Bsp[(k20 + lk + 4) * 128 + ((cb + lm) ^ sw)];
            }
#pragma unroll
            for (int mf = 0; mf < 2; mf++)
#pragma unroll
                for (int nf = 0; nf < 4; nf++)
                    mma16h(acc[mf][nf], a[mf][0], a[mf][1], a[mf][2], a[mf][3],
                           b[nf][0], b[nf][1]);
        }
    }

    // epilogue: bias + hardtanh; g_x rows padded to NMAX so no store guard
#pragma unroll
    for (int mf = 0; mf < 2; mf++) {
        int r0 = m0g + m0 + mf * 16 + lm;
#pragma unroll
        for (int nf = 0; nf < 4; nf++) {
            int c = n0 + nf * 8 + 2 * lk;
            float b0 = __ldg(bias + c), b1 = __ldg(bias + c + 1);
            float2 v0, v1;
            v0.x = clipf(acc[mf][nf][0] + b0);
            v0.y = clipf(acc[mf][nf][1] + b1);
            v1.x = clipf(acc[mf][nf][2] + b0);
            v1.y = clipf(acc[mf][nf][3] + b1);
            *(float2*)&g_x[(size_t)r0 * 128 + c]       = v0;
            *(float2*)&g_x[(size_t)(r0 + 8) * 128 + c] = v1;
        }
    }
}

// ---------------------------------------------------------------------------
// Kernel 2: fused per-hyperedge pipeline, 16 edges/iter, FP16 mma m16n8k16.
// (UNCHANGED R7 config — best measured: 50.2us)
// ---------------------------------------------------------------------------
#define ESMEM 148480

__global__ __launch_bounds__(512, 1)
void edge_mma(const int* __restrict__ members, const float* __restrict__ chebW,
              const float* __restrict__ gamma_, const float* __restrict__ beta_,
              const float* __restrict__ alpha_, const float* __restrict__ chebb,
              const float* __restrict__ linW, const float* __restrict__ linb,
              float* __restrict__ out, int E) {
    extern __shared__ unsigned char esm[];
    unsigned* Acs = (unsigned*)esm;
    unsigned* Bcs = (unsigned*)(esm + 32768);
    unsigned* Gw  = (unsigned*)(esm + 65536);
    float*    Hs  = (float*)(esm + 65536);
    unsigned* Sw  = (unsigned*)(esm + 135168);
    float*    Qsm = (float*)(esm + 139520);
    float*    red = (float*)(esm + 148224);

    const int t = threadIdx.x;
    const int lane = t & 31, w = t >> 5;
    const int lm = lane >> 2, lk = lane & 3;

    // ---- fold of prep: A = W0 + W1/7 - 47/49 W2 ; B = -W1/7 + 12/49 W2 ----
    for (int i = t; i < 2048; i += 512) {
        int k2 = i >> 5;
        int cg = (i & 31) * 4;
        const float* p0 = chebW + (2 * k2) * 128 + cg;
        const float* p1 = p0 + 128;
        float4 w00 = __ldg((const float4*)(p0));
        float4 w01 = __ldg((const float4*)(p0 + 16384));
        float4 w02 = __ldg((const float4*)(p0 + 32768));
        float4 w10 = __ldg((const float4*)(p1));
        float4 w11 = __ldg((const float4*)(p1 + 16384));
        float4 w12 = __ldg((const float4*)(p1 + 32768));
        float a0[4] = {w00.x + w01.x*(1.0f/7.0f) - w02.x*(47.0f/49.0f),
                       w00.y + w01.y*(1.0f/7.0f) - w02.y*(47.0f/49.0f),
                       w00.z + w01.z*(1.0f/7.0f) - w02.z*(47.0f/49.0f),
                       w00.w + w01.w*(1.0f/7.0f) - w02.w*(47.0f/49.0f)};
        float a1[4] = {w10.x + w11.x*(1.0f/7.0f) - w12.x*(47.0f/49.0f),
                       w10.y + w11.y*(1.0f/7.0f) - w12.y*(47.0f/49.0f),
                       w10.z + w11.z*(1.0f/7.0f) - w12.z*(47.0f/49.0f),
                       w10.w + w11.w*(1.0f/7.0f) - w12.w*(47.0f/49.0f)};
        float b0[4] = {-w01.x*(1.0f/7.0f) + w02.x*(12.0f/49.0f),
                       -w01.y*(1.0f/7.0f) + w02.y*(12.0f/49.0f),
                       -w01.z*(1.0f/7.0f) + w02.z*(12.0f/49.0f),
                       -w01.w*(1.0f/7.0f) + w02.w*(12.0f/49.0f)};
        float b1[4] = {-w11.x*(1.0f/7.0f) + w12.x*(12.0f/49.0f),
                       -w11.y*(1.0f/7.0f) + w12.y*(12.0f/49.0f),
                       -w11.z*(1.0f/7.0f) + w12.z*(12.0f/49.0f),
                       -w11.w*(1.0f/7.0f) + w12.w*(12.0f/49.0f)};
        int dst = k2 * 128 + (cg ^ (8 * (k2 & 3)));
        uint4 ua = make_uint4(pack2h(a0[0], a1[0]), pack2h(a0[1], a1[1]),
                              pack2h(a0[2], a1[2]), pack2h(a0[3], a1[3]));
        uint4 ub = make_uint4(pack2h(b0[0], b1[0]), pack2h(b0[1], b1[1]),
                              pack2h(b0[2], b1[2]), pack2h(b0[3], b1[3]));
        *(uint4*)&Acs[dst] = ua;
        *(uint4*)&Bcs[dst] = ub;
    }

    const int c4 = t & 31;
    const float4 ga4 = *(const float4*)(gamma_ + 4 * c4);
    const float4 be4 = *(const float4*)(beta_  + 4 * c4);
    const float4 al4 = *(const float4*)(alpha_ + 4 * c4);

    const int d = t & 127, quarter = t >> 7;
    const float lw0 = linW[d], lw1 = linW[128 + d];
    const float lb = __ldg(linb);

    const int m0 = (w >> 2) * 32, n0 = (w & 3) * 32, nq0 = w * 8;
    const int nIter = (E + 15) >> 4;

    __syncthreads();   // Acs/Bcs ready

    for (int it = blockIdx.x; it < nIter; it += gridDim.x) {
        const int ebase = it * 16;

        const int el = w;
        const int e = ebase + el;
        int mreg = 0;
        if (lane < 8 && e < E) mreg = __ldg(&members[e * 8 + lane]);

        // ---- stage A: gather + GraphNorm -> fp16 Gw / Sw ----
        {
            unsigned* grow = Gw + el * 8 * 68 + 2 * c4;
            unsigned* srow = Sw + el * 68 + 2 * c4;
            if (e < E) {
                float4 xv[8];
#pragma unroll
                for (int i = 0; i < 8; i++) {
                    int node = __shfl_sync(0xffffffffu, mreg, i);
                    xv[i] = *(const float4*)(g_x + (size_t)node * 128 + 4 * c4);
                }
                float4 mean = make_float4(0, 0, 0, 0);
#pragma unroll
                for (int i = 0; i < 8; i++) {
                    mean.x += xv[i].x; mean.y += xv[i].y;
                    mean.z += xv[i].z; mean.w += xv[i].w;
                }
                mean.x *= 0.125f; mean.y *= 0.125f;
                mean.z *= 0.125f; mean.w *= 0.125f;
                float4 am = make_float4(al4.x * mean.x, al4.y * mean.y,
                                        al4.z * mean.z, al4.w * mean.w);
                float4 var = make_float4(0, 0, 0, 0);
#pragma unroll
                for (int i = 0; i < 8; i++) {
                    xv[i].x -= am.x; xv[i].y -= am.y;
                    xv[i].z -= am.z; xv[i].w -= am.w;
                    var.x += xv[i].x * xv[i].x; var.y += xv[i].y * xv[i].y;
                    var.z += xv[i].z * xv[i].z; var.w += xv[i].w * xv[i].w;
                }
                float4 inv;
                inv.x = ga4.x * rsqrtf(var.x * 0.125f + EPSF);
                inv.y = ga4.y * rsqrtf(var.y * 0.125f + EPSF);
                inv.z = ga4.z * rsqrtf(var.z * 0.125f + EPSF);
                inv.w = ga4.w * rsqrtf(var.w * 0.125f + EPSF);
#pragma unroll
                for (int i = 0; i < 8; i++) {
                    uint2 u;
                    u.x = pack2h(xv[i].x * inv.x + be4.x, xv[i].y * inv.y + be4.y);
                    u.y = pack2h(xv[i].z * inv.z + be4.z, xv[i].w * inv.w + be4.w);
                    *(uint2*)(grow + i * 68) = u;
                }
                uint2 su;
                su.x = pack2h(inv.x * 8.0f * mean.x * (1.0f - al4.x) + 8.0f * be4.x,
                              inv.y * 8.0f * mean.y * (1.0f - al4.y) + 8.0f * be4.y);
                su.y = pack2h(inv.z * 8.0f * mean.z * (1.0f - al4.z) + 8.0f * be4.z,
                              inv.w * 8.0f * mean.w * (1.0f - al4.w) + 8.0f * be4.w);
                *(uint2*)srow = su;
            } else {
                uint2 z = make_uint2(0, 0);
#pragma unroll
                for (int i = 0; i < 8; i++) *(uint2*)(grow + i * 68) = z;
                *(uint2*)srow = z;
            }
        }
        __syncthreads();

        // ---- stage B: fp16 MMAs. main: g[128,128]@A ; q: S[16,128]@B ----
        float acc[2][4][4];
        float qac[4];
#pragma unroll
        for (int mf = 0; mf < 2; mf++)
#pragma unroll
            for (int nf = 0; nf < 4; nf++)
#pragma unroll
                for (int r = 0; r < 4; r++) acc[mf][nf][r] = 0.0f;
#pragma unroll
        for (int r = 0; r < 4; r++) qac[r] = 0.0f;

#pragma unroll
        for (int ks = 0; ks < 8; ks++) {
            const int k20 = ks * 8;
            const int sw = 8 * lk;
            unsigned a[2][4];
#pragma unroll
            for (int mf = 0; mf < 2; mf++) {
                int rb = m0 + mf * 16;
                a[mf][0] = Gw[(rb + lm) * 68 + k20 + lk];
                a[mf][1] = Gw[(rb + lm + 8) * 68 + k20 + lk];
                a[mf][2] = Gw[(rb + lm) * 68 + k20 + lk + 4];
                a[mf][3] = Gw[(rb + lm + 8) * 68 + k20 + lk + 4];
            }
            unsigned b[4][2];
#pragma unroll
            for (int nf = 0; nf < 4; nf++) {
                int cb = n0 + nf * 8;
                b[nf][0] = Acs[(k20 + lk) * 128 + ((cb + lm) ^ sw)];
                b[nf][1] = Acs[(k20 + lk + 4) * 128 + ((cb + lm) ^ sw)];
            }
#pragma unroll
            for (int mf = 0; mf < 2; mf++)
#pragma unroll
                for (int nf = 0; nf < 4; nf++)
                    mma16h(acc[mf][nf], a[mf][0], a[mf][1], a[mf][2], a[mf][3],
                           b[nf][0], b[nf][1]);
            unsigned sa0 = Sw[lm * 68 + k20 + lk];
            unsigned sa1 = Sw[(lm + 8) * 68 + k20 + lk];
            unsigned sa2 = Sw[lm * 68 + k20 + lk + 4];
            unsigned sa3 = Sw[(lm + 8) * 68 + k20 + lk + 4];
            unsigned qb0 = Bcs[(k20 + lk) * 128 + ((nq0 + lm) ^ sw)];
            unsigned qb1 = Bcs[(k20 + lk + 4) * 128 + ((nq0 + lm) ^ sw)];
            mma16h(qac, sa0, sa1, sa2, sa3, qb0, qb1);
        }
        {
            int c = nq0 + 2 * lk;
            float cb0 = __ldg(chebb + c), cb1 = __ldg(chebb + c + 1);
            Qsm[lm * 136 + c]           = qac[0] + cb0;
            Qsm[lm * 136 + c + 1]       = qac[1] + cb1;
            Qsm[(lm + 8) * 136 + c]     = qac[2] + cb0;
            Qsm[(lm + 8) * 136 + c + 1] = qac[3] + cb1;
        }
        __syncthreads();

        // ---- stage C: h = clip(acc + Q[e][c]) -> Hs (reuses Gw space) ----
#pragma unroll
        for (int mf = 0; mf < 2; mf++) {
            int rb = m0 + mf * 16 + lm;
            int e0 = rb >> 3;
            int e1 = (rb + 8) >> 3;
#pragma unroll
            for (int nf = 0; nf < 4; nf++) {
                int c = n0 + nf * 8 + 2 * lk;
                float2 q0 = *(const float2*)&Qsm[e0 * 136 + c];
                float2 q1 = *(const float2*)&Qsm[e1 * 136 + c];
                float2 v0, v1;
                v0.x = clipf(acc[mf][nf][0] + q0.x);
                v0.y = clipf(acc[mf][nf][1] + q0.y);
                v1.x = clipf(acc[mf][nf][2] + q1.x);
                v1.y = clipf(acc[mf][nf][3] + q1.y);
                *(float2*)&Hs[rb * 136 + c]       = v0;
                *(float2*)&Hs[(rb + 8) * 136 + c] = v1;
            }
        }
        __syncthreads();

        // ---- stage D: pooling + linear head + sigmoid (4 edges / thread) ----
        float contrib[4];
#pragma unroll
        for (int j = 0; j < 4; j++) {
            int elj = quarter * 4 + j;
            float mx = -2.0f, mn = 2.0f, ss = 0.0f;
#pragma unroll
            for (int i = 0; i < 8; i++) {
                float h = Hs[(elj * 8 + i) * 136 + d];
                mx = fmaxf(mx, h);
                mn = fminf(mn, h);
                ss += h * h;
            }
            contrib[j] = (mx - mn) * lw0 + sqrtf(ss * 0.125f) * lw1;
        }
#pragma unroll
        for (int j = 0; j < 4; j++) {
            float v = contrib[j];
            v += __shfl_xor_sync(0xffffffffu, v, 16);
            v += __shfl_xor_sync(0xffffffffu, v, 8);
            v += __shfl_xor_sync(0xffffffffu, v, 4);
            v += __shfl_xor_sync(0xffffffffu, v, 2);
            v += __shfl_xor_sync(0xffffffffu, v, 1);
            if (lane == 0) red[(quarter * 4 + j) * 4 + (w & 3)] = v;
        }
        __syncthreads();
        if (t < 16) {
            int eo = ebase + t;
            if (eo < E) {
                float* r = red + t * 4;
                float logit = r[0] + r[1] + r[2] + r[3] + lb;
                out[eo] = 1.0f / (1.0f + expf(-logit));
            }
        }
        __syncthreads();   // protect smem before next iteration
    }
}

// ---------------------------------------------------------------------------
extern "C" void kernel_launch(void* const* d_in, const int* in_sizes, int n_in,
                              void* d_out, int out_size) {
    const float* pos   = (const float*)d_in[0];
    const float* Wenc  = (const float*)d_in[1];
    const float* benc  = (const float*)d_in[2];
    const float* gam   = (const float*)d_in[3];
    const float* bet   = (const float*)d_in[4];
    const float* alp   = (const float*)d_in[5];
    const float* chebW = (const float*)d_in[6];
    const float* chebb = (const float*)d_in[7];
    const float* linW  = (const float*)d_in[8];
    const float* linb  = (const float*)d_in[9];
    const int*   membs = (const int*)d_in[10];

    int N = in_sizes[0] / FDIM;   // 50000
    int E = in_sizes[10] / 8;     // 20000

    prep_w<<<128, 256>>>(Wenc);

    cudaFuncSetAttribute(encoder_h2, cudaFuncAttributeMaxDynamicSharedMemorySize,
                         ENC_SMEM);
    encoder_h2<<<(N + 127) / 128, 512, ENC_SMEM>>>(pos, benc, N);

    cudaFuncSetAttribute(edge_mma, cudaFuncAttributeMaxDynamicSharedMemorySize,
                         ESMEM);
    int nIter = (E + 15) / 16;
    int grid = nIter < 148 ? nIter : 148;
    edge_mma<<<grid, 512, ESMEM>>>(membs, chebW, gam, bet, alp, chebb, linW,
                                   linb, (float*)d_out, E);
}

// round 13
// speedup vs baseline: 1.2335x; 1.0132x over previous
#include <cuda_runtime.h>
#include <cuda_fp16.h>
#include <math.h>
#include <stdint.h>

#define FDIM 512
#define DDIM 128
#define NMAX 50048
#define EPSF 1e-5f

// Scratch (allocation-free rule: device globals)
__device__ float g_x[(size_t)NMAX * DDIM];      // encoded node features
__device__ unsigned g_Wh[256 * 128];            // W_enc fp16, word = k-pair, [k2][n]

__device__ __forceinline__ void mma16h(float* c, unsigned a0, unsigned a1,
                                       unsigned a2, unsigned a3,
                                       unsigned b0, unsigned b1) {
    asm volatile(
        "mma.sync.aligned.m16n8k16.row.col.f32.f16.f16.f32 "
        "{%0,%1,%2,%3},{%4,%5,%6,%7},{%8,%9},{%0,%1,%2,%3};"
        : "+f"(c[0]), "+f"(c[1]), "+f"(c[2]), "+f"(c[3])
        : "r"(a0), "r"(a1), "r"(a2), "r"(a3), "r"(b0), "r"(b1));
}
__device__ __forceinline__ float clipf(float v) {
    return fminf(1.0f, fmaxf(-1.0f, v));
}
__device__ __forceinline__ unsigned pack2h(float lo, float hi) {
    __half2 h = __floats2half2_rn(lo, hi);
    return *(unsigned*)&h;
}
__device__ __forceinline__ uint32_t smem_u32(const void* p) {
    uint32_t a;
    asm("{ .reg .u64 t; cvta.to.shared.u64 t, %1; cvt.u32.u64 %0, t; }"
        : "=r"(a) : "l"(p));
    return a;
}
__device__ __forceinline__ void cpasync16(uint32_t dst, const void* src, int szr) {
    asm volatile("cp.async.ca.shared.global [%0], [%1], 16, %2;"
                 :: "r"(dst), "l"(src), "r"(szr) : "memory");
}
#define CP_COMMIT() asm volatile("cp.async.commit_group;" ::: "memory")
#define CP_WAIT1()  asm volatile("cp.async.wait_group 1;" ::: "memory")

// ---------------------------------------------------------------------------
// Kernel 0: pack W_enc to fp16 k-pair words over ALL K=512 (256 k2-rows):
//   g_Wh[k2*128+n] = (W[2k2][n], W[2k2+1][n])
// ---------------------------------------------------------------------------
__global__ void prep_w(const float* __restrict__ W) {
    int i = blockIdx.x * blockDim.x + threadIdx.x;
    if (i < 256 * 128) {
        int k2 = i >> 7, n = i & 127;
        g_Wh[i] = pack2h(W[2 * k2 * 128 + n], W[(2 * k2 + 1) * 128 + n]);
    }
}

// ---------------------------------------------------------------------------
// Kernel 1: encoder x = clip(pos @ W_enc + b, -1, 1) via FP16 mma m16n8k16.
// R13: CTA tile M=64 x N=128, 256 threads (8 warps, 2x4, warp tile 32x32),
// 3 CTAs/SM (3 independent barrier domains absorb the per-k-tile drains).
// B: cp.async 3-stage from g_Wh (zero convert). A: fp32 LDG depth-4 register
// prefetch -> pack fp16 -> STS, 3 smem stages. 1 barrier / k-tile.
// As: [row][k2] stride 20 words; Bs: [k2][n] word-swizzle n^(8*(k2&3)).
// smem: As 3x5120B @0 ; Bs 3x8192B @15360 ; total 39936B (x3 CTAs = 120KB).
// ---------------------------------------------------------------------------
#define ENC_A_BYTES (64 * 20 * 4)                     // 5120
#define ENC_B_BYTES (16 * 128 * 4)                    // 8192
#define ENC_SMEM    (3 * (ENC_A_BYTES + ENC_B_BYTES)) // 39936

__global__ __launch_bounds__(256, 3)
void encoder_h3(const float* __restrict__ pos, const float* __restrict__ bias,
                int N) {
    extern __shared__ unsigned char sm[];
    unsigned* As = (unsigned*)sm;                 // 3 stages x 1280 words
    unsigned* Bs = (unsigned*)(sm + 3 * ENC_A_BYTES);
    const uint32_t smb = smem_u32(sm);

    const int t = threadIdx.x, lane = t & 31, w = t >> 5;
    const int lm = lane >> 2, lk = lane & 3;
    const int m0 = (w >> 2) * 32, n0 = (w & 3) * 32;
    const int m0g = blockIdx.x * 64;

    // A staging: thread -> (row 0..63, k-quad of 8 floats)
    const int arow = t >> 2, aq = t & 3;
    const bool aok = (m0g + arow) < N;
    const float* ap = pos + (size_t)(m0g + arow) * FDIM + aq * 8;
    const int asoff = arow * 20 + aq * 4;
    // B staging: thread -> (k2 row 0..15, 8-word col group as 2x16B)
    const int bk2 = t >> 4, bn8 = (t & 15) * 8;
    const int bsw = 8 * (bk2 & 3);
    const uint32_t bdst0 = smb + 3 * ENC_A_BYTES +
                           (bk2 * 128 + (bn8 ^ bsw)) * 4;
    const uint32_t bdst1 = smb + 3 * ENC_A_BYTES +
                           (bk2 * 128 + ((bn8 + 4) ^ bsw)) * 4;
    const unsigned* bsrc = g_Wh + bk2 * 128 + bn8;

    float acc[2][4][4];
#pragma unroll
    for (int mf = 0; mf < 2; mf++)
#pragma unroll
        for (int nf = 0; nf < 4; nf++)
#pragma unroll
            for (int r = 0; r < 4; r++) acc[mf][nf][r] = 0.0f;

    float4 rb0[2], rb1[2];
    auto ldgA = [&](float4* r, int kt) {
        if (aok) {
            r[0] = *(const float4*)(ap + kt * 32);
            r[1] = *(const float4*)(ap + kt * 32 + 4);
        } else {
            r[0] = make_float4(0, 0, 0, 0);
            r[1] = make_float4(0, 0, 0, 0);
        }
    };
    auto stsA = [&](int s, const float4* r) {
        uint4 u = make_uint4(pack2h(r[0].x, r[0].y), pack2h(r[0].z, r[0].w),
                             pack2h(r[1].x, r[1].y), pack2h(r[1].z, r[1].w));
        *(uint4*)&As[s * 1280 + asoff] = u;
    };
    auto cpB = [&](int s, int kt) {
        cpasync16(bdst0 + s * ENC_B_BYTES, bsrc + kt * 16 * 128, 16);
        cpasync16(bdst1 + s * ENC_B_BYTES, bsrc + kt * 16 * 128 + 4, 16);
    };

    // prologue: tiles 0,1 staged; tiles 2,3 in registers
    ldgA(rb0, 0); ldgA(rb1, 1);
    cpB(0, 0); CP_COMMIT();
    cpB(1, 1); CP_COMMIT();
    stsA(0, rb0); stsA(1, rb1);
    ldgA(rb0, 2); ldgA(rb1, 3);

    for (int kt = 0; kt < 16; kt++) {
        const int s = kt % 3;
        CP_WAIT1();             // B(kt) landed (groups complete in order)
        __syncthreads();        // everyone done MMA(kt-1); A(kt) visible
        if (kt + 2 < 16) {
            float4* rb = (kt & 1) ? rb1 : rb0;
            stsA((kt + 2) % 3, rb);
            cpB((kt + 2) % 3, kt + 2);
            if (kt + 4 < 16) ldgA(rb, kt + 4);
        }
        CP_COMMIT();            // empty group when nothing issued keeps order

        const unsigned* Asp = As + s * 1280;
        const unsigned* Bsp = Bs + s * 2048;
#pragma unroll
        for (int ks = 0; ks < 2; ks++) {
            const int k20 = ks * 8;
            const int sw = 8 * lk;
            unsigned a[2][4];
#pragma unroll
            for (int mf = 0; mf < 2; mf++) {
                int rb_ = m0 + mf * 16;
                a[mf][0] = Asp[(rb_ + lm) * 20 + k20 + lk];
                a[mf][1] = Asp[(rb_ + lm + 8) * 20 + k20 + lk];
                a[mf][2] = Asp[(rb_ + lm) * 20 + k20 + lk + 4];
                a[mf][3] = Asp[(rb_ + lm + 8) * 20 + k20 + lk + 4];
            }
            unsigned b[4][2];
#pragma unroll
            for (int nf = 0; nf < 4; nf++) {
                int cb = n0 + nf * 8;
                b[nf][0] = Bsp[(k20 + lk) * 128 + ((cb + lm) ^ sw)];
                b[nf][1] = Bsp[(k20 + lk + 4) * 128 + ((cb + lm) ^ sw)];
            }
#pragma unroll
            for (int mf = 0; mf < 2; mf++)
#pragma unroll
                for (int nf = 0; nf < 4; nf++)
                    mma16h(acc[mf][nf], a[mf][0], a[mf][1], a[mf][2], a[mf][3],
                           b[nf][0], b[nf][1]);
        }
    }

    // epilogue: bias + hardtanh; NMAX = 782*64 so stores need no guard
#pragma unroll
    for (int mf = 0; mf < 2; mf++) {
        int r0 = m0g + m0 + mf * 16 + lm;
#pragma unroll
        for (int nf = 0; nf < 4; nf++) {
            int c = n0 + nf * 8 + 2 * lk;
            float b0 = __ldg(bias + c), b1 = __ldg(bias + c + 1);
            float2 v0, v1;
            v0.x = clipf(acc[mf][nf][0] + b0);
            v0.y = clipf(acc[mf][nf][1] + b1);
            v1.x = clipf(acc[mf][nf][2] + b0);
            v1.y = clipf(acc[mf][nf][3] + b1);
            *(float2*)&g_x[(size_t)r0 * 128 + c]       = v0;
            *(float2*)&g_x[(size_t)(r0 + 8) * 128 + c] = v1;
        }
    }
}

// ---------------------------------------------------------------------------
// Kernel 2: fused per-hyperedge pipeline, 16 edges/iter, FP16 mma m16n8k16.
// (UNCHANGED R7/R12 config — best measured: 50.2us)
// ---------------------------------------------------------------------------
#define ESMEM 148480

__global__ __launch_bounds__(512, 1)
void edge_mma(const int* __restrict__ members, const float* __restrict__ chebW,
              const float* __restrict__ gamma_, const float* __restrict__ beta_,
              const float* __restrict__ alpha_, const float* __restrict__ chebb,
              const float* __restrict__ linW, const float* __restrict__ linb,
              float* __restrict__ out, int E) {
    extern __shared__ unsigned char esm[];
    unsigned* Acs = (unsigned*)esm;
    unsigned* Bcs = (unsigned*)(esm + 32768);
    unsigned* Gw  = (unsigned*)(esm + 65536);
    float*    Hs  = (float*)(esm + 65536);
    unsigned* Sw  = (unsigned*)(esm + 135168);
    float*    Qsm = (float*)(esm + 139520);
    float*    red = (float*)(esm + 148224);

    const int t = threadIdx.x;
    const int lane = t & 31, w = t >> 5;
    const int lm = lane >> 2, lk = lane & 3;

    // ---- fold of prep: A = W0 + W1/7 - 47/49 W2 ; B = -W1/7 + 12/49 W2 ----
    for (int i = t; i < 2048; i += 512) {
        int k2 = i >> 5;
        int cg = (i & 31) * 4;
        const float* p0 = chebW + (2 * k2) * 128 + cg;
        const float* p1 = p0 + 128;
        float4 w00 = __ldg((const float4*)(p0));
        float4 w01 = __ldg((const float4*)(p0 + 16384));
        float4 w02 = __ldg((const float4*)(p0 + 32768));
        float4 w10 = __ldg((const float4*)(p1));
        float4 w11 = __ldg((const float4*)(p1 + 16384));
        float4 w12 = __ldg((const float4*)(p1 + 32768));
        float a0[4] = {w00.x + w01.x*(1.0f/7.0f) - w02.x*(47.0f/49.0f),
                       w00.y + w01.y*(1.0f/7.0f) - w02.y*(47.0f/49.0f),
                       w00.z + w01.z*(1.0f/7.0f) - w02.z*(47.0f/49.0f),
                       w00.w + w01.w*(1.0f/7.0f) - w02.w*(47.0f/49.0f)};
        float a1[4] = {w10.x + w11.x*(1.0f/7.0f) - w12.x*(47.0f/49.0f),
                       w10.y + w11.y*(1.0f/7.0f) - w12.y*(47.0f/49.0f),
                       w10.z + w11.z*(1.0f/7.0f) - w12.z*(47.0f/49.0f),
                       w10.w + w11.w*(1.0f/7.0f) - w12.w*(47.0f/49.0f)};
        float b0[4] = {-w01.x*(1.0f/7.0f) + w02.x*(12.0f/49.0f),
                       -w01.y*(1.0f/7.0f) + w02.y*(12.0f/49.0f),
                       -w01.z*(1.0f/7.0f) + w02.z*(12.0f/49.0f),
                       -w01.w*(1.0f/7.0f) + w02.w*(12.0f/49.0f)};
        float b1[4] = {-w11.x*(1.0f/7.0f) + w12.x*(12.0f/49.0f),
                       -w11.y*(1.0f/7.0f) + w12.y*(12.0f/49.0f),
                       -w11.z*(1.0f/7.0f) + w12.z*(12.0f/49.0f),
                       -w11.w*(1.0f/7.0f) + w12.w*(12.0f/49.0f)};
        int dst = k2 * 128 + (cg ^ (8 * (k2 & 3)));
        uint4 ua = make_uint4(pack2h(a0[0], a1[0]), pack2h(a0[1], a1[1]),
                              pack2h(a0[2], a1[2]), pack2h(a0[3], a1[3]));
        uint4 ub = make_uint4(pack2h(b0[0], b1[0]), pack2h(b0[1], b1[1]),
                              pack2h(b0[2], b1[2]), pack2h(b0[3], b1[3]));
        *(uint4*)&Acs[dst] = ua;
        *(uint4*)&Bcs[dst] = ub;
    }

    const int c4 = t & 31;
    const float4 ga4 = *(const float4*)(gamma_ + 4 * c4);
    const float4 be4 = *(const float4*)(beta_  + 4 * c4);
    const float4 al4 = *(const float4*)(alpha_ + 4 * c4);

    const int d = t & 127, quarter = t >> 7;
    const float lw0 = linW[d], lw1 = linW[128 + d];
    const float lb = __ldg(linb);

    const int m0 = (w >> 2) * 32, n0 = (w & 3) * 32, nq0 = w * 8;
    const int nIter = (E + 15) >> 4;

    __syncthreads();   // Acs/Bcs ready

    for (int it = blockIdx.x; it < nIter; it += gridDim.x) {
        const int ebase = it * 16;

        const int el = w;
        const int e = ebase + el;
        int mreg = 0;
        if (lane < 8 && e < E) mreg = __ldg(&members[e * 8 + lane]);

        // ---- stage A: gather + GraphNorm -> fp16 Gw / Sw ----
        {
            unsigned* grow = Gw + el * 8 * 68 + 2 * c4;
            unsigned* srow = Sw + el * 68 + 2 * c4;
            if (e < E) {
                float4 xv[8];
#pragma unroll
                for (int i = 0; i < 8; i++) {
                    int node = __shfl_sync(0xffffffffu, mreg, i);
                    xv[i] = *(const float4*)(g_x + (size_t)node * 128 + 4 * c4);
                }
                float4 mean = make_float4(0, 0, 0, 0);
#pragma unroll
                for (int i = 0; i < 8; i++) {
                    mean.x += xv[i].x; mean.y += xv[i].y;
                    mean.z += xv[i].z; mean.w += xv[i].w;
                }
                mean.x *= 0.125f; mean.y *= 0.125f;
                mean.z *= 0.125f; mean.w *= 0.125f;
                float4 am = make_float4(al4.x * mean.x, al4.y * mean.y,
                                        al4.z * mean.z, al4.w * mean.w);
                float4 var = make_float4(0, 0, 0, 0);
#pragma unroll
                for (int i = 0; i < 8; i++) {
                    xv[i].x -= am.x; xv[i].y -= am.y;
                    xv[i].z -= am.z; xv[i].w -= am.w;
                    var.x += xv[i].x * xv[i].x; var.y += xv[i].y * xv[i].y;
                    var.z += xv[i].z * xv[i].z; var.w += xv[i].w * xv[i].w;
                }
                float4 inv;
                inv.x = ga4.x * rsqrtf(var.x * 0.125f + EPSF);
                inv.y = ga4.y * rsqrtf(var.y * 0.125f + EPSF);
                inv.z = ga4.z * rsqrtf(var.z * 0.125f + EPSF);
                inv.w = ga4.w * rsqrtf(var.w * 0.125f + EPSF);
#pragma unroll
                for (int i = 0; i < 8; i++) {
                    uint2 u;
                    u.x = pack2h(xv[i].x * inv.x + be4.x, xv[i].y * inv.y + be4.y);
                    u.y = pack2h(xv[i].z * inv.z + be4.z, xv[i].w * inv.w + be4.w);
                    *(uint2*)(grow + i * 68) = u;
                }
                uint2 su;
                su.x = pack2h(inv.x * 8.0f * mean.x * (1.0f - al4.x) + 8.0f * be4.x,
                              inv.y * 8.0f * mean.y * (1.0f - al4.y) + 8.0f * be4.y);
                su.y = pack2h(inv.z * 8.0f * mean.z * (1.0f - al4.z) + 8.0f * be4.z,
                              inv.w * 8.0f * mean.w * (1.0f - al4.w) + 8.0f * be4.w);
                *(uint2*)srow = su;
            } else {
                uint2 z = make_uint2(0, 0);
#pragma unroll
                for (int i = 0; i < 8; i++) *(uint2*)(grow + i * 68) = z;
                *(uint2*)srow = z;
            }
        }
        __syncthreads();

        // ---- stage B: fp16 MMAs. main: g[128,128]@A ; q: S[16,128]@B ----
        float acc[2][4][4];
        float qac[4];
#pragma unroll
        for (int mf = 0; mf < 2; mf++)
#pragma unroll
            for (int nf = 0; nf < 4; nf++)
#pragma unroll
                for (int r = 0; r < 4; r++) acc[mf][nf][r] = 0.0f;
#pragma unroll
        for (int r = 0; r < 4; r++) qac[r] = 0.0f;

#pragma unroll
        for (int ks = 0; ks < 8; ks++) {
            const int k20 = ks * 8;
            const int sw = 8 * lk;
            unsigned a[2][4];
#pragma unroll
            for (int mf = 0; mf < 2; mf++) {
                int rb = m0 + mf * 16;
                a[mf][0] = Gw[(rb + lm) * 68 + k20 + lk];
                a[mf][1] = Gw[(rb + lm + 8) * 68 + k20 + lk];
                a[mf][2] = Gw[(rb + lm) * 68 + k20 + lk + 4];
                a[mf][3] = Gw[(rb + lm + 8) * 68 + k20 + lk + 4];
            }
            unsigned b[4][2];
#pragma unroll
            for (int nf = 0; nf < 4; nf++) {
                int cb = n0 + nf * 8;
                b[nf][0] = Acs[(k20 + lk) * 128 + ((cb + lm) ^ sw)];
                b[nf][1] = Acs[(k20 + lk + 4) * 128 + ((cb + lm) ^ sw)];
            }
#pragma unroll
            for (int mf = 0; mf < 2; mf++)
#pragma unroll
                for (int nf = 0; nf < 4; nf++)
                    mma16h(acc[mf][nf], a[mf][0], a[mf][1], a[mf][2], a[mf][3],
                           b[nf][0], b[nf][1]);
            unsigned sa0 = Sw[lm * 68 + k20 + lk];
            unsigned sa1 = Sw[(lm + 8) * 68 + k20 + lk];
            unsigned sa2 = Sw[lm * 68 + k20 + lk + 4];
            unsigned sa3 = Sw[(lm + 8) * 68 + k20 + lk + 4];
            unsigned qb0 = Bcs[(k20 + lk) * 128 + ((nq0 + lm) ^ sw)];
            unsigned qb1 = Bcs[(k20 + lk + 4) * 128 + ((nq0 + lm) ^ sw)];
            mma16h(qac, sa0, sa1, sa2, sa3, qb0, qb1);
        }
        {
            int c = nq0 + 2 * lk;
            float cb0 = __ldg(chebb + c), cb1 = __ldg(chebb + c + 1);
            Qsm[lm * 136 + c]           = qac[0] + cb0;
            Qsm[lm * 136 + c + 1]       = qac[1] + cb1;
            Qsm[(lm + 8) * 136 + c]     = qac[2] + cb0;
            Qsm[(lm + 8) * 136 + c + 1] = qac[3] + cb1;
        }
        __syncthreads();

        // ---- stage C: h = clip(acc + Q[e][c]) -> Hs (reuses Gw space) ----
#pragma unroll
        for (int mf = 0; mf < 2; mf++) {
            int rb = m0 + mf * 16 + lm;
            int e0 = rb >> 3;
            int e1 = (rb + 8) >> 3;
#pragma unroll
            for (int nf = 0; nf < 4; nf++) {
                int c = n0 + nf * 8 + 2 * lk;
                float2 q0 = *(const float2*)&Qsm[e0 * 136 + c];
                float2 q1 = *(const float2*)&Qsm[e1 * 136 + c];
                float2 v0, v1;
                v0.x = clipf(acc[mf][nf][0] + q0.x);
                v0.y = clipf(acc[mf][nf][1] + q0.y);
                v1.x = clipf(acc[mf][nf][2] + q1.x);
                v1.y = clipf(acc[mf][nf][3] + q1.y);
                *(float2*)&Hs[rb * 136 + c]       = v0;
                *(float2*)&Hs[(rb + 8) * 136 + c] = v1;
            }
        }
        __syncthreads();

        // ---- stage D: pooling + linear head + sigmoid (4 edges / thread) ----
        float contrib[4];
#pragma unroll
        for (int j = 0; j < 4; j++) {
            int elj = quarter * 4 + j;
            float mx = -2.0f, mn = 2.0f, ss = 0.0f;
#pragma unroll
            for (int i = 0; i < 8; i++) {
                float h = Hs[(elj * 8 + i) * 136 + d];
                mx = fmaxf(mx, h);
                mn = fminf(mn, h);
                ss += h * h;
            }
            contrib[j] = (mx - mn) * lw0 + sqrtf(ss * 0.125f) * lw1;
        }
#pragma unroll
        for (int j = 0; j < 4; j++) {
            float v = contrib[j];
            v += __shfl_xor_sync(0xffffffffu, v, 16);
            v += __shfl_xor_sync(0xffffffffu, v, 8);
            v += __shfl_xor_sync(0xffffffffu, v, 4);
            v += __shfl_xor_sync(0xffffffffu, v, 2);
            v += __shfl_xor_sync(0xffffffffu, v, 1);
            if (lane == 0) red[(quarter * 4 + j) * 4 + (w & 3)] = v;
        }
        __syncthreads();
        if (t < 16) {
            int eo = ebase + t;
            if (eo < E) {
                float* r = red + t * 4;
                float logit = r[0] + r[1] + r[2] + r[3] + lb;
                out[eo] = 1.0f / (1.0f + expf(-logit));
            }
        }
        __syncthreads();   // protect smem before next iteration
    }
}

// ---------------------------------------------------------------------------
extern "C" void kernel_launch(void* const* d_in, const int* in_sizes, int n_in,
                              void* d_out, int out_size) {
    const float* pos   = (const float*)d_in[0];
    const float* Wenc  = (const float*)d_in[1];
    const float* benc  = (const float*)d_in[2];
    const float* gam   = (const float*)d_in[3];
    const float* bet   = (const float*)d_in[4];
    const float* alp   = (const float*)d_in[5];
    const float* chebW = (const float*)d_in[6];
    const float* chebb = (const float*)d_in[7];
    const float* linW  = (const float*)d_in[8];
    const float* linb  = (const float*)d_in[9];
    const int*   membs = (const int*)d_in[10];

    int N = in_sizes[0] / FDIM;   // 50000
    int E = in_sizes[10] / 8;     // 20000

    prep_w<<<128, 256>>>(Wenc);

    cudaFuncSetAttribute(encoder_h3, cudaFuncAttributeMaxDynamicSharedMemorySize,
                         ENC_SMEM);
    encoder_h3<<<(N + 63) / 64, 256, ENC_SMEM>>>(pos, benc, N);

    cudaFuncSetAttribute(edge_mma, cudaFuncAttributeMaxDynamicSharedMemorySize,
                         ESMEM);
    int nIter = (E + 15) / 16;
    int grid = nIter < 148 ? nIter : 148;
    edge_mma<<<grid, 512, ESMEM>>>(membs, chebW, gam, bet, alp, chebb, linW,
                                   linb, (float*)d_out, E);
}